// round 5
// baseline (speedup 1.0000x reference)
#include <cuda_runtime.h>
#include <cuda_bf16.h>
#include <math.h>
#include <stdint.h>

// Problem constants
#define BB 4
#define DD 1024
#define NHH 16
#define DHH 64
#define LQQ 1024
#define NPP 4

typedef __nv_bfloat16 bf16;
typedef __nv_bfloat162 bf162;

// ---------------- scratch (device globals; no allocation allowed) ----------------
__device__ bf16  g_qn_bf   [BB * LQQ * DD];
__device__ bf16  g_fn_bf   [BB * 4 * LQQ * DD];
__device__ bf16  g_wbf     [5177344];               // all 8 weight matrices in bf16
__device__ bf16  g_val_bf  [BB * 4 * LQQ * DD];
__device__ float g_off     [BB * LQQ * 512];
__device__ float g_attw    [BB * LQQ * 256];        // raw logits (softmax fused into sampling)
__device__ bf16  g_samp_bf [BB * LQQ * DD];
__device__ float g_attn    [BB * LQQ * DD];
__device__ bf16  g_attn1_bf[BB * LQQ * DD];
__device__ bf16  g_val2_bf [BB * LQQ * DD];
__device__ float g_off2    [BB * LQQ * 128];
__device__ float g_attw2   [BB * LQQ * 64];
__device__ bf16  g_samp2_bf[BB * LQQ * DD];
__device__ float g_attn2   [BB * LQQ * DD];

// weight offsets within g_wbf
#define W_CAVW 0
#define W_CAOW 1048576
#define W_CAAW 1572864
#define W_CAPW 1835008
#define W_SAVW 2883584
#define W_SAOW 3932160
#define W_SAPW 4128768
#define W_SAAW 4063232

// ---------------- helpers ----------------
__device__ __forceinline__ void mma_bf16(float4& d, const uint32_t* a, uint32_t b0, uint32_t b1) {
    asm("mma.sync.aligned.m16n8k16.row.col.f32.bf16.bf16.f32 "
        "{%0,%1,%2,%3}, {%4,%5,%6,%7}, {%8,%9}, {%0,%1,%2,%3};"
        : "+f"(d.x), "+f"(d.y), "+f"(d.z), "+f"(d.w)
        : "r"(a[0]), "r"(a[1]), "r"(a[2]), "r"(a[3]), "r"(b0), "r"(b1));
}

__device__ __forceinline__ void cp_async16(uint32_t dst, const void* src) {
    asm volatile("cp.async.cg.shared.global [%0], [%1], 16;" :: "r"(dst), "l"(src) : "memory");
}

__device__ __forceinline__ void ldsm4(uint32_t* r, uint32_t addr) {
    asm volatile("ldmatrix.sync.aligned.m8n8.x4.shared.b16 {%0,%1,%2,%3}, [%4];"
                 : "=r"(r[0]), "=r"(r[1]), "=r"(r[2]), "=r"(r[3]) : "r"(addr));
}

// ---------------- bf16 tensor-core GEMM: C[M,N] = A[M,K] @ W[N,K]^T + bias ----------------
// Block tile 128 x NT, BK=32, 256 threads = 8 warps (2 x 4 m x n), 4-stage cp.async pipe.
// SMEM row = 64B (32 bf16); 16B chunk swizzle c' = c ^ ((row>>1)&3). Fragments via ldmatrix.x4.
template<int NT, bool BF16_OUT>
__global__ void __launch_bounds__(256, 2) bf16_gemm_kernel(
    const bf16* __restrict__ A, const bf16* __restrict__ W,
    const float* __restrict__ bias, void* __restrict__ Cv,
    int M, int N, int K)
{
    constexpr int NFRAG = NT / 32;       // n frags per warp
    constexpr int NPAIR = NFRAG / 2;     // B ldmatrix.x4 per kstep
    constexpr int B_CH  = NT / 64;       // B cp.async chunks per thread
    constexpr int ASZ   = 128 * 64;      // 8192 B
    constexpr int BSZ   = NT * 64;
    constexpr int STG   = ASZ + BSZ;
    constexpr int S     = 4;

    extern __shared__ __align__(16) char dsm[];

    const int tid = threadIdx.x;
    const int lane = tid & 31;
    const int w = tid >> 5;
    const int warp_m = w >> 2;
    const int warp_n = w & 3;
    const int g = lane >> 2, t = lane & 3;
    const int m0 = blockIdx.y * 128;
    const int n0 = blockIdx.x * NT;

    const uint32_t smem_u32 = (uint32_t)__cvta_generic_to_shared(dsm);

    // cp.async thread assignment
    const int arow0 = tid >> 2, ac0 = tid & 3;
    const int arow1 = (tid + 256) >> 2, ac1 = tid & 3;

    // ldmatrix per-lane base addresses
    const int rowA = warp_m * 64 + (lane & 15);          // +mf*16
    const int khA  = lane >> 4;
    const int swA  = (rowA >> 1) & 3;
    const int rowB = warp_n * (NFRAG * 8) + ((lane >> 4) & 1) * 8 + (lane & 7);  // +pair*16
    const int khB  = (lane >> 3) & 1;
    const int swB  = (rowB >> 1) & 3;
    // chunk offsets for ks=0,1
    const uint32_t axo[2] = { (uint32_t)(((0 + khA) ^ swA) << 4), (uint32_t)(((2 + khA) ^ swA) << 4) };
    const uint32_t bxo[2] = { (uint32_t)(((0 + khB) ^ swB) << 4), (uint32_t)(((2 + khB) ^ swB) << 4) };
    const uint32_t aBase = smem_u32 + rowA * 64;
    const uint32_t bBase = smem_u32 + ASZ + rowB * 64;

    float4 acc[4][NFRAG];
    #pragma unroll
    for (int i = 0; i < 4; i++)
        #pragma unroll
        for (int j = 0; j < NFRAG; j++) acc[i][j] = make_float4(0.f,0.f,0.f,0.f);

    auto issue = [&](int stage, int k0) {
        uint32_t sa = smem_u32 + stage * STG;
        uint32_t sb = sa + ASZ;
        {
            int row = arow0, c = ac0;
            cp_async16(sa + row*64 + ((c ^ ((row>>1)&3))<<4),
                       A + (size_t)(m0+row)*K + k0 + c*8);
            row = arow1; c = ac1;
            cp_async16(sa + row*64 + ((c ^ ((row>>1)&3))<<4),
                       A + (size_t)(m0+row)*K + k0 + c*8);
        }
        #pragma unroll
        for (int i = 0; i < B_CH; i++) {
            int e = tid + i*256, row = e>>2, c = e&3;
            cp_async16(sb + row*64 + ((c ^ ((row>>1)&3))<<4),
                       W + (size_t)(n0+row)*K + k0 + c*8);
        }
        asm volatile("cp.async.commit_group;" ::: "memory");
    };

    const int NCH = K >> 5;    // 32
    issue(0, 0); issue(1, 32); issue(2, 64);

    for (int it = 0; it < NCH; it++) {
        asm volatile("cp.async.wait_group 2;" ::: "memory");
        __syncthreads();
        if (it + S - 1 < NCH) issue((it + S - 1) & (S - 1), (it + S - 1) << 5);
        else asm volatile("cp.async.commit_group;" ::: "memory");

        const uint32_t stoff = (uint32_t)((it & (S - 1)) * STG);

        #pragma unroll
        for (int ks = 0; ks < 2; ks++) {
            uint32_t a[4][4];
            uint32_t b[NPAIR][4];
            #pragma unroll
            for (int mf = 0; mf < 4; mf++)
                ldsm4(a[mf], aBase + stoff + mf * 1024 + axo[ks]);
            #pragma unroll
            for (int p = 0; p < NPAIR; p++)
                ldsm4(b[p], bBase + stoff + p * 1024 + bxo[ks]);
            #pragma unroll
            for (int mf = 0; mf < 4; mf++)
                #pragma unroll
                for (int nf = 0; nf < NFRAG; nf++)
                    mma_bf16(acc[mf][nf], a[mf], b[nf >> 1][(nf & 1) * 2], b[nf >> 1][(nf & 1) * 2 + 1]);
        }
    }

    // epilogue
    #pragma unroll
    for (int mf = 0; mf < 4; mf++) {
        int mr = m0 + warp_m*64 + mf*16 + g;
        #pragma unroll
        for (int nf = 0; nf < NFRAG; nf++) {
            int nc = n0 + (warp_n*NFRAG + nf)*8 + 2*t;
            float b0 = __ldg(bias + nc), b1 = __ldg(bias + nc + 1);
            float ox = acc[mf][nf].x + b0, oy = acc[mf][nf].y + b1;
            float oz = acc[mf][nf].z + b0, ow = acc[mf][nf].w + b1;
            if (BF16_OUT) {
                bf16* C = (bf16*)Cv;
                *(bf162*)(C + (size_t)mr * N + nc)       = __floats2bfloat162_rn(ox, oy);
                *(bf162*)(C + (size_t)(mr + 8) * N + nc) = __floats2bfloat162_rn(oz, ow);
            } else {
                float* C = (float*)Cv;
                *(float2*)(C + (size_t)mr * N + nc)       = make_float2(ox, oy);
                *(float2*)(C + (size_t)(mr + 8) * N + nc) = make_float2(oz, ow);
            }
        }
    }
}

// ---------------- weight fp32 -> bf16 conversion ----------------
__global__ void __launch_bounds__(256) wcvt_kernel(
    const float* w0, const float* w1, const float* w2, const float* w3,
    const float* w4, const float* w5, const float* w6, const float* w7)
{
    int b = blockIdx.x;
    const float* src; bf16* dst;
    if      (b < 1024) { src = w0; dst = g_wbf + W_CAVW; }
    else if (b < 1536) { src = w1; dst = g_wbf + W_CAOW; b -= 1024; }
    else if (b < 1792) { src = w2; dst = g_wbf + W_CAAW; b -= 1536; }
    else if (b < 2816) { src = w3; dst = g_wbf + W_CAPW; b -= 1792; }
    else if (b < 3840) { src = w4; dst = g_wbf + W_SAVW; b -= 2816; }
    else if (b < 3968) { src = w5; dst = g_wbf + W_SAOW; b -= 3840; }
    else if (b < 4032) { src = w6; dst = g_wbf + W_SAAW; b -= 3968; }
    else               { src = w7; dst = g_wbf + W_SAPW; b -= 4032; }
    int idx = b * 1024 + threadIdx.x * 4;
    float4 v = *(const float4*)(src + idx);
    *(bf162*)(dst + idx)     = __floats2bfloat162_rn(v.x, v.y);
    *(bf162*)(dst + idx + 2) = __floats2bfloat162_rn(v.z, v.w);
}

// ---------------- layernorm -> bf16 out ----------------
__global__ void __launch_bounds__(256) layernorm_bf_kernel(
    const float* __restrict__ in, const float* __restrict__ g, const float* __restrict__ b,
    bf16* __restrict__ out)
{
    int r = blockIdx.x;
    const float* x = in + (size_t)r * DD;
    bf16* y = out + (size_t)r * DD;
    int t = threadIdx.x;

    float4 v = ((const float4*)x)[t];
    float s  = v.x + v.y + v.z + v.w;
    float ss = v.x*v.x + v.y*v.y + v.z*v.z + v.w*v.w;
    #pragma unroll
    for (int o = 16; o > 0; o >>= 1) {
        s  += __shfl_xor_sync(0xffffffffu, s,  o);
        ss += __shfl_xor_sync(0xffffffffu, ss, o);
    }
    __shared__ float sh_s[8], sh_ss[8];
    int wid = t >> 5, lane = t & 31;
    if (lane == 0) { sh_s[wid] = s; sh_ss[wid] = ss; }
    __syncthreads();
    s = 0.f; ss = 0.f;
    #pragma unroll
    for (int i = 0; i < 8; i++) { s += sh_s[i]; ss += sh_ss[i]; }
    float mean = s * (1.0f / DD);
    float var  = ss * (1.0f / DD) - mean * mean;
    float inv  = rsqrtf(var + 1e-6f);

    float4 gg = ((const float4*)g)[t];
    float4 bb2 = ((const float4*)b)[t];
    ((bf162*)y)[2*t]   = __floats2bfloat162_rn((v.x-mean)*inv*gg.x + bb2.x, (v.y-mean)*inv*gg.y + bb2.y);
    ((bf162*)y)[2*t+1] = __floats2bfloat162_rn((v.z-mean)*inv*gg.z + bb2.z, (v.w-mean)*inv*gg.w + bb2.w);
}

__global__ void __launch_bounds__(256) layernorm4_bf_kernel(
    const float* __restrict__ s0, const float* __restrict__ s1,
    const float* __restrict__ s2, const float* __restrict__ s3,
    const float* __restrict__ g, const float* __restrict__ b, bf16* __restrict__ out)
{
    int r = blockIdx.x;
    int level = r >> 12;
    int rr = r & 4095;
    const float* src = (level == 0) ? s0 : (level == 1) ? s1 : (level == 2) ? s2 : s3;
    const float* x = src + (size_t)rr * DD;
    int n = rr >> 10, q = rr & 1023;
    bf16* y = out + ((size_t)n * (4 * LQQ) + level * LQQ + q) * DD;
    int t = threadIdx.x;

    float4 v = ((const float4*)x)[t];
    float s  = v.x + v.y + v.z + v.w;
    float ss = v.x*v.x + v.y*v.y + v.z*v.z + v.w*v.w;
    #pragma unroll
    for (int o = 16; o > 0; o >>= 1) {
        s  += __shfl_xor_sync(0xffffffffu, s,  o);
        ss += __shfl_xor_sync(0xffffffffu, ss, o);
    }
    __shared__ float sh_s[8], sh_ss[8];
    int wid = t >> 5, lane = t & 31;
    if (lane == 0) { sh_s[wid] = s; sh_ss[wid] = ss; }
    __syncthreads();
    s = 0.f; ss = 0.f;
    #pragma unroll
    for (int i = 0; i < 8; i++) { s += sh_s[i]; ss += sh_ss[i]; }
    float mean = s * (1.0f / DD);
    float var  = ss * (1.0f / DD) - mean * mean;
    float inv  = rsqrtf(var + 1e-6f);

    float4 gg = ((const float4*)g)[t];
    float4 bb2 = ((const float4*)b)[t];
    ((bf162*)y)[2*t]   = __floats2bfloat162_rn((v.x-mean)*inv*gg.x + bb2.x, (v.y-mean)*inv*gg.y + bb2.y);
    ((bf162*)y)[2*t+1] = __floats2bfloat162_rn((v.z-mean)*inv*gg.z + bb2.z, (v.w-mean)*inv*gg.w + bb2.w);
}

// ---------------- deformable sampling with fused softmax ----------------
// block 256 thr = 4 heads x 64 ch, grid (NH/4, LQ, B)
template<int NL>
__global__ void __launch_bounds__(256) sample_kernel(
    const bf16* __restrict__ val,
    const float* __restrict__ off,
    const float* __restrict__ logits,   // raw attention logits
    bf16* __restrict__ out)
{
    const int h  = blockIdx.x * 4 + (threadIdx.x >> 6);
    const int lq = blockIdx.y;
    const int n  = blockIdx.z;
    const int dh = threadIdx.x & 63;

    const float refx = ((lq & 31) + 0.5f) * 0.03125f;
    const float refy = ((lq >> 5) + 0.5f) * 0.03125f;

    const float* op = off    + (size_t)(n * LQQ + lq) * (NL * 128) + h * (NL * 8);
    const float* lp = logits + (size_t)(n * LQQ + lq) * (NL * 64)  + h * (NL * 4);
    const bf16* vb = val + (size_t)n * (NL * LQQ) * DD + h * DHH + dh;

    // fused softmax over NL*NPP logits (redundant per-thread, cheap)
    float wgt[NL * 4];
    float mx = -1e30f;
    #pragma unroll
    for (int i = 0; i < NL; i++) {
        float4 l4 = __ldg((const float4*)(lp + i * 4));
        wgt[i*4+0] = l4.x; wgt[i*4+1] = l4.y; wgt[i*4+2] = l4.z; wgt[i*4+3] = l4.w;
    }
    #pragma unroll
    for (int i = 0; i < NL * 4; i++) mx = fmaxf(mx, wgt[i]);
    float sum = 0.f;
    #pragma unroll
    for (int i = 0; i < NL * 4; i++) { wgt[i] = __expf(wgt[i] - mx); sum += wgt[i]; }
    float invs = 1.0f / sum;

    float acc = 0.f;
    #pragma unroll
    for (int l = 0; l < NL; l++) {
        const bf16* vl = vb + (size_t)l * LQQ * DD;
        #pragma unroll
        for (int p = 0; p < NPP; p++) {
            float ox = __ldg(op + l * 8 + p * 2 + 0);
            float oy = __ldg(op + l * 8 + p * 2 + 1);
            float x = (refx + ox * 0.03125f) * 32.f - 0.5f;
            float y = (refy + oy * 0.03125f) * 32.f - 0.5f;
            float x0f = floorf(x), y0f = floorf(y);
            int xi = (int)x0f, yi = (int)y0f;
            float fx = x - x0f, fy = y - y0f;
            float wv = wgt[l * 4 + p] * invs;
            float w00 = (1.f - fy) * (1.f - fx) * wv;
            float w01 = (1.f - fy) * fx * wv;
            float w10 = fy * (1.f - fx) * wv;
            float w11 = fy * fx * wv;
            bool xv0 = (xi >= 0) && (xi < 32);
            bool xv1 = (xi + 1 >= 0) && (xi + 1 < 32);
            if (yi >= 0 && yi < 32) {
                const bf16* row = vl + (size_t)yi * 32 * DD;
                if (xv0) acc += w00 * __bfloat162float(__ldg(row + (size_t)xi * DD));
                if (xv1) acc += w01 * __bfloat162float(__ldg(row + (size_t)(xi + 1) * DD));
            }
            if (yi + 1 >= 0 && yi + 1 < 32) {
                const bf16* row = vl + (size_t)(yi + 1) * 32 * DD;
                if (xv0) acc += w10 * __bfloat162float(__ldg(row + (size_t)xi * DD));
                if (xv1) acc += w11 * __bfloat162float(__ldg(row + (size_t)(xi + 1) * DD));
            }
        }
    }
    out[(size_t)(n * LQQ + lq) * DD + h * DHH + dh] = __float2bfloat16(acc);
}

// ---------------- final residual combine ----------------
__global__ void __launch_bounds__(256) combine_kernel(
    const float* __restrict__ src3, const float* __restrict__ gamma1, const float* __restrict__ gamma2,
    const float* __restrict__ attn, const float* __restrict__ attn2, float* __restrict__ out)
{
    int idx = blockIdx.x * blockDim.x + threadIdx.x;
    int d = idx & (DD - 1);
    out[idx] = src3[idx] + gamma1[d] * (attn[idx] + gamma2[d] * attn2[idx]);
}

// ---------------- host launcher ----------------
extern "C" void kernel_launch(void* const* d_in, const int* in_sizes, int n_in,
                              void* d_out, int out_size)
{
    const float* src0 = (const float*)d_in[0];
    const float* src1 = (const float*)d_in[1];
    const float* src2 = (const float*)d_in[2];
    const float* src3 = (const float*)d_in[3];
    const float* qn_g = (const float*)d_in[4];
    const float* qn_b = (const float*)d_in[5];
    const float* fn_g = (const float*)d_in[6];
    const float* fn_b = (const float*)d_in[7];
    const float* n1_g = (const float*)d_in[8];
    const float* n1_b = (const float*)d_in[9];
    const float* gamma1 = (const float*)d_in[10];
    const float* gamma2 = (const float*)d_in[11];
    const float* ca_vw = (const float*)d_in[12];
    const float* ca_vb = (const float*)d_in[13];
    const float* ca_ow = (const float*)d_in[14];
    const float* ca_ob = (const float*)d_in[15];
    const float* ca_aw = (const float*)d_in[16];
    const float* ca_ab = (const float*)d_in[17];
    const float* ca_pw = (const float*)d_in[18];
    const float* ca_pb = (const float*)d_in[19];
    const float* sa_vw = (const float*)d_in[20];
    const float* sa_vb = (const float*)d_in[21];
    const float* sa_ow = (const float*)d_in[22];
    const float* sa_ob = (const float*)d_in[23];
    const float* sa_aw = (const float*)d_in[24];
    const float* sa_ab = (const float*)d_in[25];
    const float* sa_pw = (const float*)d_in[26];
    const float* sa_pb = (const float*)d_in[27];
    float* out = (float*)d_out;

    static bool attr_done = false;
    if (!attr_done) {
        cudaFuncSetAttribute(bf16_gemm_kernel<128,true>,  cudaFuncAttributeMaxDynamicSharedMemorySize, 65536);
        cudaFuncSetAttribute(bf16_gemm_kernel<128,false>, cudaFuncAttributeMaxDynamicSharedMemorySize, 65536);
        cudaFuncSetAttribute(bf16_gemm_kernel<64,false>,  cudaFuncAttributeMaxDynamicSharedMemorySize, 49152);
        attr_done = true;
    }

    bf16 *qn, *fn, *wb, *val, *samp, *attn1, *val2, *samp2;
    float *off, *attw, *attn, *off2, *attw2, *attn2;
    cudaGetSymbolAddress((void**)&qn,    g_qn_bf);
    cudaGetSymbolAddress((void**)&fn,    g_fn_bf);
    cudaGetSymbolAddress((void**)&wb,    g_wbf);
    cudaGetSymbolAddress((void**)&val,   g_val_bf);
    cudaGetSymbolAddress((void**)&off,   g_off);
    cudaGetSymbolAddress((void**)&attw,  g_attw);
    cudaGetSymbolAddress((void**)&samp,  g_samp_bf);
    cudaGetSymbolAddress((void**)&attn,  g_attn);
    cudaGetSymbolAddress((void**)&attn1, g_attn1_bf);
    cudaGetSymbolAddress((void**)&val2,  g_val2_bf);
    cudaGetSymbolAddress((void**)&off2,  g_off2);
    cudaGetSymbolAddress((void**)&attw2, g_attw2);
    cudaGetSymbolAddress((void**)&samp2, g_samp2_bf);
    cudaGetSymbolAddress((void**)&attn2, g_attn2);

    const int ROWS_Q = BB * LQQ;        // 4096
    const int ROWS_F = BB * 4 * LQQ;    // 16384

    // 0) weights -> bf16
    wcvt_kernel<<<5056, 256>>>(ca_vw, ca_ow, ca_aw, ca_pw, sa_vw, sa_ow, sa_aw, sa_pw);

    // 1) layernorms (bf16 out)
    layernorm_bf_kernel<<<ROWS_Q, 256>>>(src3, qn_g, qn_b, qn);
    layernorm4_bf_kernel<<<4 * ROWS_Q, 256>>>(src0, src1, src2, src3, fn_g, fn_b, fn);

    // 2) CA projections (attw left as raw logits; softmax fused into sampling)
    bf16_gemm_kernel<128,true ><<<dim3(8, 128), 256, 65536>>>(fn, wb + W_CAVW, ca_vb, val,  ROWS_F, DD,  DD);
    bf16_gemm_kernel<128,false><<<dim3(4, 32),  256, 65536>>>(qn, wb + W_CAOW, ca_ob, off,  ROWS_Q, 512, DD);
    bf16_gemm_kernel<128,false><<<dim3(2, 32),  256, 65536>>>(qn, wb + W_CAAW, ca_ab, attw, ROWS_Q, 256, DD);

    // 3) CA sampling (+softmax) + output proj
    sample_kernel<4><<<dim3(NHH/4, LQQ, BB), 256>>>(val, off, attw, samp);
    bf16_gemm_kernel<128,false><<<dim3(8, 32), 256, 65536>>>(samp, wb + W_CAPW, ca_pb, attn, ROWS_Q, DD, DD);

    // 4) layernorm -> attn1 (bf16)
    layernorm_bf_kernel<<<ROWS_Q, 256>>>(attn, n1_g, n1_b, attn1);

    // 5) SA projections
    bf16_gemm_kernel<128,true ><<<dim3(8, 32), 256, 65536>>>(attn1, wb + W_SAVW, sa_vb, val2,  ROWS_Q, DD,  DD);
    bf16_gemm_kernel<128,false><<<dim3(1, 32), 256, 65536>>>(attn1, wb + W_SAOW, sa_ob, off2,  ROWS_Q, 128, DD);
    bf16_gemm_kernel<64, false><<<dim3(1, 32), 256, 49152>>>(attn1, wb + W_SAAW, sa_ab, attw2, ROWS_Q, 64,  DD);

    // 6) SA sampling (+softmax) + output proj
    sample_kernel<1><<<dim3(NHH/4, LQQ, BB), 256>>>(val2, off2, attw2, samp2);
    bf16_gemm_kernel<128,false><<<dim3(8, 32), 256, 65536>>>(samp2, wb + W_SAPW, sa_pb, attn2, ROWS_Q, DD, DD);

    // 7) residual combine
    combine_kernel<<<(BB * LQQ * DD) / 256, 256>>>(src3, gamma1, gamma2, attn, attn2, out);
}

// round 7
// speedup vs baseline: 1.3124x; 1.3124x over previous
#include <cuda_runtime.h>
#include <cuda_bf16.h>
#include <math.h>
#include <stdint.h>

// Problem constants
#define BB 4
#define DD 1024
#define NHH 16
#define DHH 64
#define LQQ 1024
#define NPP 4

typedef __nv_bfloat16 bf16;
typedef __nv_bfloat162 bf162;

// ---------------- scratch (device globals; no allocation allowed) ----------------
__device__ bf16  g_qn_bf   [BB * LQQ * DD];
__device__ bf16  g_fn_bf   [BB * 4 * LQQ * DD];
__device__ bf16  g_wbf     [5177344];               // all 8 weight matrices in bf16
__device__ bf16  g_val_bf  [BB * 4 * LQQ * DD];
__device__ float g_off     [BB * LQQ * 512];
__device__ float g_attw    [BB * LQQ * 256];
__device__ bf16  g_samp_bf [BB * LQQ * DD];
__device__ float g_attn    [BB * LQQ * DD];
__device__ bf16  g_attn1_bf[BB * LQQ * DD];
__device__ bf16  g_val2_bf [BB * LQQ * DD];
__device__ float g_off2    [BB * LQQ * 128];
__device__ float g_attw2   [BB * LQQ * 64];
__device__ bf16  g_samp2_bf[BB * LQQ * DD];
__device__ float g_attn2   [BB * LQQ * DD];

// weight offsets within g_wbf
#define W_CAVW 0
#define W_CAOW 1048576
#define W_CAAW 1572864
#define W_CAPW 1835008
#define W_SAVW 2883584
#define W_SAOW 3932160
#define W_SAPW 4128768
#define W_SAAW 4063232

// ---------------- helpers ----------------
__device__ __forceinline__ void mma_bf16(float4& d, const uint32_t* a, uint32_t b0, uint32_t b1) {
    asm("mma.sync.aligned.m16n8k16.row.col.f32.bf16.bf16.f32 "
        "{%0,%1,%2,%3}, {%4,%5,%6,%7}, {%8,%9}, {%0,%1,%2,%3};"
        : "+f"(d.x), "+f"(d.y), "+f"(d.z), "+f"(d.w)
        : "r"(a[0]), "r"(a[1]), "r"(a[2]), "r"(a[3]), "r"(b0), "r"(b1));
}

__device__ __forceinline__ void cp_async16(uint32_t dst, const void* src) {
    asm volatile("cp.async.cg.shared.global [%0], [%1], 16;" :: "r"(dst), "l"(src) : "memory");
}

__device__ __forceinline__ void ldsm4(uint32_t* r, uint32_t addr) {
    asm volatile("ldmatrix.sync.aligned.m8n8.x4.shared.b16 {%0,%1,%2,%3}, [%4];"
                 : "=r"(r[0]), "=r"(r[1]), "=r"(r[2]), "=r"(r[3]) : "r"(addr));
}

// ---------------- bf16 tensor-core GEMM: C[M,N] = A[M,K] @ W[N,K]^T + bias ----------------
// Block tile 128 x NT, BK=64, 256 threads = 8 warps (2 x 4 m x n), 3-stage cp.async pipe.
// SMEM row = 128B (64 bf16) = 8 chunks of 16B; chunk swizzle c' = c ^ (row&7).
template<int NT, bool BF16_OUT>
__global__ void __launch_bounds__(256, 2) bf16_gemm_kernel(
    const bf16* __restrict__ A, const bf16* __restrict__ W,
    const float* __restrict__ bias, void* __restrict__ Cv,
    int M, int N, int K)
{
    constexpr int NFRAG = NT / 32;        // n frags per warp
    constexpr int NPAIR = NFRAG / 2;      // B ldmatrix.x4 per kstep
    constexpr int A_CH  = 4;              // A cp.async chunks per thread (128*8/256)
    constexpr int B_CH  = NT / 32;        // B cp.async chunks per thread
    constexpr int ASZ   = 128 * 128;      // 16384 B
    constexpr int BSZ   = NT * 128;
    constexpr int STG   = ASZ + BSZ;
    constexpr int S     = 3;

    extern __shared__ __align__(16) char dsm[];

    const int tid = threadIdx.x;
    const int lane = tid & 31;
    const int w = tid >> 5;
    const int warp_m = w >> 2;
    const int warp_n = w & 3;
    const int g = lane >> 2, t = lane & 3;
    const int m0 = blockIdx.y * 128;
    const int n0 = blockIdx.x * NT;

    const uint32_t smem_u32 = (uint32_t)__cvta_generic_to_shared(dsm);

    // ldmatrix per-lane addressing
    const int rowA = warp_m * 64 + (lane & 15);                 // +mf*16 (doesn't change row&7)
    const int khA  = lane >> 4;                                 // 0,1
    const int swA  = rowA & 7;
    const int rowB = warp_n * (NFRAG * 8) + ((lane >> 4) & 1) * 8 + (lane & 7);  // +pair*16
    const int khB  = (lane >> 3) & 1;
    const int swB  = rowB & 7;
    uint32_t axo[4], bxo[4];
    #pragma unroll
    for (int ks = 0; ks < 4; ks++) {
        axo[ks] = (uint32_t)(((ks * 2 + khA) ^ swA) << 4);
        bxo[ks] = (uint32_t)(((ks * 2 + khB) ^ swB) << 4);
    }
    const uint32_t aBase = smem_u32 + rowA * 128;
    const uint32_t bBase = smem_u32 + ASZ + rowB * 128;

    float4 acc[4][NFRAG];
    #pragma unroll
    for (int i = 0; i < 4; i++)
        #pragma unroll
        for (int j = 0; j < NFRAG; j++) acc[i][j] = make_float4(0.f,0.f,0.f,0.f);

    auto issue = [&](int stage, int k0) {
        uint32_t sa = smem_u32 + stage * STG;
        uint32_t sb = sa + ASZ;
        #pragma unroll
        for (int i = 0; i < A_CH; i++) {
            int e = i * 256 + tid, row = e >> 3, c = e & 7;
            cp_async16(sa + row * 128 + ((c ^ (row & 7)) << 4),
                       A + (size_t)(m0 + row) * K + k0 + c * 8);
        }
        #pragma unroll
        for (int i = 0; i < B_CH; i++) {
            int e = i * 256 + tid, row = e >> 3, c = e & 7;
            cp_async16(sb + row * 128 + ((c ^ (row & 7)) << 4),
                       W + (size_t)(n0 + row) * K + k0 + c * 8);
        }
        asm volatile("cp.async.commit_group;" ::: "memory");
    };

    const int NCH = K >> 6;    // 16
    issue(0, 0); issue(1, 64);

    for (int it = 0; it < NCH; it++) {
        asm volatile("cp.async.wait_group 1;" ::: "memory");
        __syncthreads();
        if (it + 2 < NCH) issue((it + 2) % S, (it + 2) << 6);
        else asm volatile("cp.async.commit_group;" ::: "memory");

        const uint32_t stoff = (uint32_t)((it % S) * STG);

        #pragma unroll
        for (int ks = 0; ks < 4; ks++) {
            uint32_t a[4][4];
            uint32_t b[NPAIR][4];
            #pragma unroll
            for (int mf = 0; mf < 4; mf++)
                ldsm4(a[mf], aBase + stoff + mf * 2048 + axo[ks]);
            #pragma unroll
            for (int p = 0; p < NPAIR; p++)
                ldsm4(b[p], bBase + stoff + p * 2048 + bxo[ks]);
            #pragma unroll
            for (int mf = 0; mf < 4; mf++)
                #pragma unroll
                for (int nf = 0; nf < NFRAG; nf++)
                    mma_bf16(acc[mf][nf], a[mf], b[nf >> 1][(nf & 1) * 2], b[nf >> 1][(nf & 1) * 2 + 1]);
        }
    }

    // epilogue
    #pragma unroll
    for (int mf = 0; mf < 4; mf++) {
        int mr = m0 + warp_m*64 + mf*16 + g;
        #pragma unroll
        for (int nf = 0; nf < NFRAG; nf++) {
            int nc = n0 + (warp_n*NFRAG + nf)*8 + 2*t;
            float b0 = __ldg(bias + nc), b1 = __ldg(bias + nc + 1);
            float ox = acc[mf][nf].x + b0, oy = acc[mf][nf].y + b1;
            float oz = acc[mf][nf].z + b0, ow = acc[mf][nf].w + b1;
            if (BF16_OUT) {
                bf16* C = (bf16*)Cv;
                *(bf162*)(C + (size_t)mr * N + nc)       = __floats2bfloat162_rn(ox, oy);
                *(bf162*)(C + (size_t)(mr + 8) * N + nc) = __floats2bfloat162_rn(oz, ow);
            } else {
                float* C = (float*)Cv;
                *(float2*)(C + (size_t)mr * N + nc)       = make_float2(ox, oy);
                *(float2*)(C + (size_t)(mr + 8) * N + nc) = make_float2(oz, ow);
            }
        }
    }
}

// ---------------- weight fp32 -> bf16 conversion ----------------
__global__ void __launch_bounds__(256) wcvt_kernel(
    const float* w0, const float* w1, const float* w2, const float* w3,
    const float* w4, const float* w5, const float* w6, const float* w7)
{
    int b = blockIdx.x;
    const float* src; bf16* dst;
    if      (b < 1024) { src = w0; dst = g_wbf + W_CAVW; }
    else if (b < 1536) { src = w1; dst = g_wbf + W_CAOW; b -= 1024; }
    else if (b < 1792) { src = w2; dst = g_wbf + W_CAAW; b -= 1536; }
    else if (b < 2816) { src = w3; dst = g_wbf + W_CAPW; b -= 1792; }
    else if (b < 3840) { src = w4; dst = g_wbf + W_SAVW; b -= 2816; }
    else if (b < 3968) { src = w5; dst = g_wbf + W_SAOW; b -= 3840; }
    else if (b < 4032) { src = w6; dst = g_wbf + W_SAAW; b -= 3968; }
    else               { src = w7; dst = g_wbf + W_SAPW; b -= 4032; }
    int idx = b * 1024 + threadIdx.x * 4;
    float4 v = *(const float4*)(src + idx);
    *(bf162*)(dst + idx)     = __floats2bfloat162_rn(v.x, v.y);
    *(bf162*)(dst + idx + 2) = __floats2bfloat162_rn(v.z, v.w);
}

// ---------------- layernorm -> bf16 out ----------------
__global__ void __launch_bounds__(256) layernorm_bf_kernel(
    const float* __restrict__ in, const float* __restrict__ g, const float* __restrict__ b,
    bf16* __restrict__ out)
{
    int r = blockIdx.x;
    const float* x = in + (size_t)r * DD;
    bf16* y = out + (size_t)r * DD;
    int t = threadIdx.x;

    float4 v = ((const float4*)x)[t];
    float s  = v.x + v.y + v.z + v.w;
    float ss = v.x*v.x + v.y*v.y + v.z*v.z + v.w*v.w;
    #pragma unroll
    for (int o = 16; o > 0; o >>= 1) {
        s  += __shfl_xor_sync(0xffffffffu, s,  o);
        ss += __shfl_xor_sync(0xffffffffu, ss, o);
    }
    __shared__ float sh_s[8], sh_ss[8];
    int wid = t >> 5, lane = t & 31;
    if (lane == 0) { sh_s[wid] = s; sh_ss[wid] = ss; }
    __syncthreads();
    s = 0.f; ss = 0.f;
    #pragma unroll
    for (int i = 0; i < 8; i++) { s += sh_s[i]; ss += sh_ss[i]; }
    float mean = s * (1.0f / DD);
    float var  = ss * (1.0f / DD) - mean * mean;
    float inv  = rsqrtf(var + 1e-6f);

    float4 gg = ((const float4*)g)[t];
    float4 bb2 = ((const float4*)b)[t];
    ((bf162*)y)[2*t]   = __floats2bfloat162_rn((v.x-mean)*inv*gg.x + bb2.x, (v.y-mean)*inv*gg.y + bb2.y);
    ((bf162*)y)[2*t+1] = __floats2bfloat162_rn((v.z-mean)*inv*gg.z + bb2.z, (v.w-mean)*inv*gg.w + bb2.w);
}

__global__ void __launch_bounds__(256) layernorm4_bf_kernel(
    const float* __restrict__ s0, const float* __restrict__ s1,
    const float* __restrict__ s2, const float* __restrict__ s3,
    const float* __restrict__ g, const float* __restrict__ b, bf16* __restrict__ out)
{
    int r = blockIdx.x;
    int level = r >> 12;
    int rr = r & 4095;
    const float* src = (level == 0) ? s0 : (level == 1) ? s1 : (level == 2) ? s2 : s3;
    const float* x = src + (size_t)rr * DD;
    int n = rr >> 10, q = rr & 1023;
    bf16* y = out + ((size_t)n * (4 * LQQ) + level * LQQ + q) * DD;
    int t = threadIdx.x;

    float4 v = ((const float4*)x)[t];
    float s  = v.x + v.y + v.z + v.w;
    float ss = v.x*v.x + v.y*v.y + v.z*v.z + v.w*v.w;
    #pragma unroll
    for (int o = 16; o > 0; o >>= 1) {
        s  += __shfl_xor_sync(0xffffffffu, s,  o);
        ss += __shfl_xor_sync(0xffffffffu, ss, o);
    }
    __shared__ float sh_s[8], sh_ss[8];
    int wid = t >> 5, lane = t & 31;
    if (lane == 0) { sh_s[wid] = s; sh_ss[wid] = ss; }
    __syncthreads();
    s = 0.f; ss = 0.f;
    #pragma unroll
    for (int i = 0; i < 8; i++) { s += sh_s[i]; ss += sh_ss[i]; }
    float mean = s * (1.0f / DD);
    float var  = ss * (1.0f / DD) - mean * mean;
    float inv  = rsqrtf(var + 1e-6f);

    float4 gg = ((const float4*)g)[t];
    float4 bb2 = ((const float4*)b)[t];
    ((bf162*)y)[2*t]   = __floats2bfloat162_rn((v.x-mean)*inv*gg.x + bb2.x, (v.y-mean)*inv*gg.y + bb2.y);
    ((bf162*)y)[2*t+1] = __floats2bfloat162_rn((v.z-mean)*inv*gg.z + bb2.z, (v.w-mean)*inv*gg.w + bb2.w);
}

// ---------------- softmax over P contiguous values ----------------
template<int P>
__global__ void softmax_kernel(float* __restrict__ w, int ngroups)
{
    int gid = blockIdx.x * blockDim.x + threadIdx.x;
    if (gid >= ngroups) return;
    float* p = w + (size_t)gid * P;
    float mx = p[0];
    #pragma unroll
    for (int i = 1; i < P; i++) mx = fmaxf(mx, p[i]);
    float s = 0.f;
    float e[P];
    #pragma unroll
    for (int i = 0; i < P; i++) { e[i] = __expf(p[i] - mx); s += e[i]; }
    float inv = 1.0f / s;
    #pragma unroll
    for (int i = 0; i < P; i++) p[i] = e[i] * inv;
}

// ---------------- deformable sampling (bf162 gathers, 2 channels/thread) ----------------
// block 256 thr = 8 heads x 32 lanes, grid (NH/8, LQ, B)
template<int NL>
__global__ void __launch_bounds__(256) sample_kernel(
    const bf16* __restrict__ val,
    const float* __restrict__ off,
    const float* __restrict__ attw,   // softmaxed
    bf16* __restrict__ out)
{
    const int h  = blockIdx.x * 8 + (threadIdx.x >> 5);
    const int lq = blockIdx.y;
    const int n  = blockIdx.z;
    const int c2 = threadIdx.x & 31;      // channel pair

    const float refx = ((lq & 31) + 0.5f) * 0.03125f;
    const float refy = ((lq >> 5) + 0.5f) * 0.03125f;

    const float* op = off  + (size_t)(n * LQQ + lq) * (NL * 128) + h * (NL * 8);
    const float* wp = attw + (size_t)(n * LQQ + lq) * (NL * 64)  + h * (NL * 4);
    const bf16* vb = val + (size_t)n * (NL * LQQ) * DD + h * DHH + 2 * c2;

    float accx = 0.f, accy = 0.f;
    #pragma unroll
    for (int l = 0; l < NL; l++) {
        const bf16* vl = vb + (size_t)l * LQQ * DD;
        #pragma unroll
        for (int p = 0; p < NPP; p++) {
            float ox = __ldg(op + l * 8 + p * 2 + 0);
            float oy = __ldg(op + l * 8 + p * 2 + 1);
            float x = (refx + ox * 0.03125f) * 32.f - 0.5f;
            float y = (refy + oy * 0.03125f) * 32.f - 0.5f;
            float x0f = floorf(x), y0f = floorf(y);
            int xi = (int)x0f, yi = (int)y0f;
            float fx = x - x0f, fy = y - y0f;
            float wv = __ldg(wp + l * 4 + p);
            float w00 = (1.f - fy) * (1.f - fx) * wv;
            float w01 = (1.f - fy) * fx * wv;
            float w10 = fy * (1.f - fx) * wv;
            float w11 = fy * fx * wv;
            bool xv0 = (xi >= 0) && (xi < 32);
            bool xv1 = (xi + 1 >= 0) && (xi + 1 < 32);
            if (yi >= 0 && yi < 32) {
                const bf16* row = vl + (size_t)yi * 32 * DD;
                if (xv0) { bf162 v2 = __ldg((const bf162*)(row + (size_t)xi * DD));
                           accx += w00 * __bfloat162float(v2.x); accy += w00 * __bfloat162float(v2.y); }
                if (xv1) { bf162 v2 = __ldg((const bf162*)(row + (size_t)(xi + 1) * DD));
                           accx += w01 * __bfloat162float(v2.x); accy += w01 * __bfloat162float(v2.y); }
            }
            if (yi + 1 >= 0 && yi + 1 < 32) {
                const bf16* row = vl + (size_t)(yi + 1) * 32 * DD;
                if (xv0) { bf162 v2 = __ldg((const bf162*)(row + (size_t)xi * DD));
                           accx += w10 * __bfloat162float(v2.x); accy += w10 * __bfloat162float(v2.y); }
                if (xv1) { bf162 v2 = __ldg((const bf162*)(row + (size_t)(xi + 1) * DD));
                           accx += w11 * __bfloat162float(v2.x); accy += w11 * __bfloat162float(v2.y); }
            }
        }
    }
    *(bf162*)(out + (size_t)(n * LQQ + lq) * DD + h * DHH + 2 * c2) = __floats2bfloat162_rn(accx, accy);
}

// ---------------- final residual combine ----------------
__global__ void __launch_bounds__(256) combine_kernel(
    const float* __restrict__ src3, const float* __restrict__ gamma1, const float* __restrict__ gamma2,
    const float* __restrict__ attn, const float* __restrict__ attn2, float* __restrict__ out)
{
    int idx = blockIdx.x * blockDim.x + threadIdx.x;
    int d = idx & (DD - 1);
    out[idx] = src3[idx] + gamma1[d] * (attn[idx] + gamma2[d] * attn2[idx]);
}

// ---------------- host launcher ----------------
extern "C" void kernel_launch(void* const* d_in, const int* in_sizes, int n_in,
                              void* d_out, int out_size)
{
    const float* src0 = (const float*)d_in[0];
    const float* src1 = (const float*)d_in[1];
    const float* src2 = (const float*)d_in[2];
    const float* src3 = (const float*)d_in[3];
    const float* qn_g = (const float*)d_in[4];
    const float* qn_b = (const float*)d_in[5];
    const float* fn_g = (const float*)d_in[6];
    const float* fn_b = (const float*)d_in[7];
    const float* n1_g = (const float*)d_in[8];
    const float* n1_b = (const float*)d_in[9];
    const float* gamma1 = (const float*)d_in[10];
    const float* gamma2 = (const float*)d_in[11];
    const float* ca_vw = (const float*)d_in[12];
    const float* ca_vb = (const float*)d_in[13];
    const float* ca_ow = (const float*)d_in[14];
    const float* ca_ob = (const float*)d_in[15];
    const float* ca_aw = (const float*)d_in[16];
    const float* ca_ab = (const float*)d_in[17];
    const float* ca_pw = (const float*)d_in[18];
    const float* ca_pb = (const float*)d_in[19];
    const float* sa_vw = (const float*)d_in[20];
    const float* sa_vb = (const float*)d_in[21];
    const float* sa_ow = (const float*)d_in[22];
    const float* sa_ob = (const float*)d_in[23];
    const float* sa_aw = (const float*)d_in[24];
    const float* sa_ab = (const float*)d_in[25];
    const float* sa_pw = (const float*)d_in[26];
    const float* sa_pb = (const float*)d_in[27];
    float* out = (float*)d_out;

    static bool attr_done = false;
    if (!attr_done) {
        cudaFuncSetAttribute(bf16_gemm_kernel<128,true>,  cudaFuncAttributeMaxDynamicSharedMemorySize, 98304);
        cudaFuncSetAttribute(bf16_gemm_kernel<128,false>, cudaFuncAttributeMaxDynamicSharedMemorySize, 98304);
        cudaFuncSetAttribute(bf16_gemm_kernel<64,false>,  cudaFuncAttributeMaxDynamicSharedMemorySize, 73728);
        attr_done = true;
    }

    bf16 *qn, *fn, *wb, *val, *samp, *attn1, *val2, *samp2;
    float *off, *attw, *attn, *off2, *attw2, *attn2;
    cudaGetSymbolAddress((void**)&qn,    g_qn_bf);
    cudaGetSymbolAddress((void**)&fn,    g_fn_bf);
    cudaGetSymbolAddress((void**)&wb,    g_wbf);
    cudaGetSymbolAddress((void**)&val,   g_val_bf);
    cudaGetSymbolAddress((void**)&off,   g_off);
    cudaGetSymbolAddress((void**)&attw,  g_attw);
    cudaGetSymbolAddress((void**)&samp,  g_samp_bf);
    cudaGetSymbolAddress((void**)&attn,  g_attn);
    cudaGetSymbolAddress((void**)&attn1, g_attn1_bf);
    cudaGetSymbolAddress((void**)&val2,  g_val2_bf);
    cudaGetSymbolAddress((void**)&off2,  g_off2);
    cudaGetSymbolAddress((void**)&attw2, g_attw2);
    cudaGetSymbolAddress((void**)&samp2, g_samp2_bf);
    cudaGetSymbolAddress((void**)&attn2, g_attn2);

    const int ROWS_Q = BB * LQQ;        // 4096
    const int ROWS_F = BB * 4 * LQQ;    // 16384

    // 0) weights -> bf16
    wcvt_kernel<<<5056, 256>>>(ca_vw, ca_ow, ca_aw, ca_pw, sa_vw, sa_ow, sa_aw, sa_pw);

    // 1) layernorms (bf16 out)
    layernorm_bf_kernel<<<ROWS_Q, 256>>>(src3, qn_g, qn_b, qn);
    layernorm4_bf_kernel<<<4 * ROWS_Q, 256>>>(src0, src1, src2, src3, fn_g, fn_b, fn);

    // 2) CA projections
    bf16_gemm_kernel<128,true ><<<dim3(8, 128), 256, 98304>>>(fn, wb + W_CAVW, ca_vb, val,  ROWS_F, DD,  DD);
    bf16_gemm_kernel<128,false><<<dim3(4, 32),  256, 98304>>>(qn, wb + W_CAOW, ca_ob, off,  ROWS_Q, 512, DD);
    bf16_gemm_kernel<128,false><<<dim3(2, 32),  256, 98304>>>(qn, wb + W_CAAW, ca_ab, attw, ROWS_Q, 256, DD);
    softmax_kernel<16><<<(BB * LQQ * NHH + 255) / 256, 256>>>(attw, BB * LQQ * NHH);

    // 3) CA sampling + output proj
    sample_kernel<4><<<dim3(NHH/8, LQQ, BB), 256>>>(val, off, attw, samp);
    bf16_gemm_kernel<128,false><<<dim3(8, 32), 256, 98304>>>(samp, wb + W_CAPW, ca_pb, attn, ROWS_Q, DD, DD);

    // 4) layernorm -> attn1 (bf16)
    layernorm_bf_kernel<<<ROWS_Q, 256>>>(attn, n1_g, n1_b, attn1);

    // 5) SA projections
    bf16_gemm_kernel<128,true ><<<dim3(8, 32), 256, 98304>>>(attn1, wb + W_SAVW, sa_vb, val2,  ROWS_Q, DD,  DD);
    bf16_gemm_kernel<128,false><<<dim3(1, 32), 256, 98304>>>(attn1, wb + W_SAOW, sa_ob, off2,  ROWS_Q, 128, DD);
    bf16_gemm_kernel<64, false><<<dim3(1, 32), 256, 73728>>>(attn1, wb + W_SAAW, sa_ab, attw2, ROWS_Q, 64,  DD);
    softmax_kernel<4><<<(BB * LQQ * NHH + 255) / 256, 256>>>(attw2, BB * LQQ * NHH);

    // 6) SA sampling + output proj
    sample_kernel<1><<<dim3(NHH/8, LQQ, BB), 256>>>(val2, off2, attw2, samp2);
    bf16_gemm_kernel<128,false><<<dim3(8, 32), 256, 98304>>>(samp2, wb + W_SAPW, sa_pb, attn2, ROWS_Q, DD, DD);

    // 7) residual combine
    combine_kernel<<<(BB * LQQ * DD) / 256, 256>>>(src3, gamma1, gamma2, attn, attn2, out);
}

// round 8
// speedup vs baseline: 1.3595x; 1.0359x over previous
#include <cuda_runtime.h>
#include <cuda_bf16.h>
#include <math.h>
#include <stdint.h>

// Problem constants
#define BB 4
#define DD 1024
#define NHH 16
#define DHH 64
#define LQQ 1024
#define NPP 4

typedef __nv_bfloat16 bf16;
typedef __nv_bfloat162 bf162;

// ---------------- scratch (device globals; no allocation allowed) ----------------
__device__ bf16  g_qn_bf   [BB * LQQ * DD];
__device__ bf16  g_fn_bf   [BB * 4 * LQQ * DD];
__device__ bf16  g_wbf     [5177344];
__device__ bf16  g_val_bf  [BB * 4 * LQQ * DD];
__device__ float g_off     [BB * LQQ * 512];
__device__ float g_attw    [BB * LQQ * 256];
__device__ bf16  g_samp_bf [BB * LQQ * DD];
__device__ float g_attn    [BB * LQQ * DD];
__device__ bf16  g_attn1_bf[BB * LQQ * DD];
__device__ bf16  g_val2_bf [BB * LQQ * DD];
__device__ float g_off2    [BB * LQQ * 128];
__device__ float g_attw2   [BB * LQQ * 64];
__device__ bf16  g_samp2_bf[BB * LQQ * DD];

// weight offsets within g_wbf
#define W_CAVW 0
#define W_CAOW 1048576
#define W_CAAW 1572864
#define W_CAPW 1835008
#define W_SAVW 2883584
#define W_SAOW 3932160
#define W_SAPW 4128768
#define W_SAAW 4063232

// ---------------- helpers ----------------
__device__ __forceinline__ void mma_bf16(float4& d, const uint32_t* a, uint32_t b0, uint32_t b1) {
    asm("mma.sync.aligned.m16n8k16.row.col.f32.bf16.bf16.f32 "
        "{%0,%1,%2,%3}, {%4,%5,%6,%7}, {%8,%9}, {%0,%1,%2,%3};"
        : "+f"(d.x), "+f"(d.y), "+f"(d.z), "+f"(d.w)
        : "r"(a[0]), "r"(a[1]), "r"(a[2]), "r"(a[3]), "r"(b0), "r"(b1));
}

__device__ __forceinline__ void cp_async16(uint32_t dst, const void* src) {
    asm volatile("cp.async.cg.shared.global [%0], [%1], 16;" :: "r"(dst), "l"(src) : "memory");
}

__device__ __forceinline__ void ldsm4(uint32_t* r, uint32_t addr) {
    asm volatile("ldmatrix.sync.aligned.m8n8.x4.shared.b16 {%0,%1,%2,%3}, [%4];"
                 : "=r"(r[0]), "=r"(r[1]), "=r"(r[2]), "=r"(r[3]) : "r"(addr));
}

// ---------------- bf16 tensor-core GEMM: C[M,N] = A[M,K] @ W[N,K]^T + bias ----------------
// Block tile 128 x NT, BK=64, 128 threads = 4 warps in 2x2 (warp tile 64 x NT/2).
// 3-stage cp.async pipe. SMEM row = 128B; 16B chunk swizzle c' = c ^ (row&7).
// MODE: 0 = f32 out, 1 = bf16 out, 2 = fused residual combine (f32 out).
template<int NT, int MODE>
__global__ void __launch_bounds__(128, 2) bf16_gemm_kernel(
    const bf16* __restrict__ A, const bf16* __restrict__ W,
    const float* __restrict__ bias, void* __restrict__ Cv,
    const float* __restrict__ src3, const float* __restrict__ attn,
    const float* __restrict__ gamma1, const float* __restrict__ gamma2,
    int M, int N, int K)
{
    constexpr int NFRAG = NT / 16;        // n frags per warp (warp covers NT/2 cols)
    constexpr int NPAIR = NFRAG / 2;      // B ldmatrix.x4 per kstep
    constexpr int A_CH  = 8;              // 128 rows * 8 chunks / 128 threads
    constexpr int B_CH  = NT / 16;        // NT rows * 8 chunks / 128 threads
    constexpr int ASZ   = 128 * 128;      // 16384 B
    constexpr int BSZ   = NT * 128;
    constexpr int STG   = ASZ + BSZ;
    constexpr int S     = 3;

    extern __shared__ __align__(16) char dsm[];

    const int tid = threadIdx.x;
    const int lane = tid & 31;
    const int w = tid >> 5;               // 0..3
    const int warp_m = w >> 1;            // 0..1
    const int warp_n = w & 1;             // 0..1
    const int g = lane >> 2, t = lane & 3;
    const int m0 = blockIdx.y * 128;
    const int n0 = blockIdx.x * NT;

    const uint32_t smem_u32 = (uint32_t)__cvta_generic_to_shared(dsm);

    // ldmatrix per-lane addressing
    const int rowA = warp_m * 64 + (lane & 15);                        // +mf*16
    const int khA  = lane >> 4;
    const int swA  = rowA & 7;
    const int rowB = warp_n * (NT / 2) + ((lane >> 4) & 1) * 8 + (lane & 7);  // +pair*16
    const int khB  = (lane >> 3) & 1;
    const int swB  = rowB & 7;
    uint32_t axo[4], bxo[4];
    #pragma unroll
    for (int ks = 0; ks < 4; ks++) {
        axo[ks] = (uint32_t)(((ks * 2 + khA) ^ swA) << 4);
        bxo[ks] = (uint32_t)(((ks * 2 + khB) ^ swB) << 4);
    }
    const uint32_t aBase = smem_u32 + rowA * 128;
    const uint32_t bBase = smem_u32 + ASZ + rowB * 128;

    float4 acc[4][NFRAG];
    #pragma unroll
    for (int i = 0; i < 4; i++)
        #pragma unroll
        for (int j = 0; j < NFRAG; j++) acc[i][j] = make_float4(0.f,0.f,0.f,0.f);

    auto issue = [&](int stage, int k0) {
        uint32_t sa = smem_u32 + stage * STG;
        uint32_t sb = sa + ASZ;
        #pragma unroll
        for (int i = 0; i < A_CH; i++) {
            int e = i * 128 + tid, row = e >> 3, c = e & 7;
            cp_async16(sa + row * 128 + ((c ^ (row & 7)) << 4),
                       A + (size_t)(m0 + row) * K + k0 + c * 8);
        }
        #pragma unroll
        for (int i = 0; i < B_CH; i++) {
            int e = i * 128 + tid, row = e >> 3, c = e & 7;
            cp_async16(sb + row * 128 + ((c ^ (row & 7)) << 4),
                       W + (size_t)(n0 + row) * K + k0 + c * 8);
        }
        asm volatile("cp.async.commit_group;" ::: "memory");
    };

    const int NCH = K >> 6;    // 16
    issue(0, 0); issue(1, 64);

    for (int it = 0; it < NCH; it++) {
        asm volatile("cp.async.wait_group 1;" ::: "memory");
        __syncthreads();
        if (it + 2 < NCH) issue((it + 2) % S, (it + 2) << 6);
        else asm volatile("cp.async.commit_group;" ::: "memory");

        const uint32_t stoff = (uint32_t)((it % S) * STG);

        #pragma unroll
        for (int ks = 0; ks < 4; ks++) {
            uint32_t a[4][4];
            uint32_t b[NPAIR][4];
            #pragma unroll
            for (int mf = 0; mf < 4; mf++)
                ldsm4(a[mf], aBase + stoff + mf * 2048 + axo[ks]);
            #pragma unroll
            for (int p = 0; p < NPAIR; p++)
                ldsm4(b[p], bBase + stoff + p * 2048 + bxo[ks]);
            #pragma unroll
            for (int mf = 0; mf < 4; mf++)
                #pragma unroll
                for (int nf = 0; nf < NFRAG; nf++)
                    mma_bf16(acc[mf][nf], a[mf], b[nf >> 1][(nf & 1) * 2], b[nf >> 1][(nf & 1) * 2 + 1]);
        }
    }

    // epilogue
    #pragma unroll
    for (int mf = 0; mf < 4; mf++) {
        int mr = m0 + warp_m*64 + mf*16 + g;
        #pragma unroll
        for (int nf = 0; nf < NFRAG; nf++) {
            int nc = n0 + warp_n*(NT/2) + nf*8 + 2*t;
            float b0 = __ldg(bias + nc), b1 = __ldg(bias + nc + 1);
            float ox = acc[mf][nf].x + b0, oy = acc[mf][nf].y + b1;
            float oz = acc[mf][nf].z + b0, ow = acc[mf][nf].w + b1;
            if (MODE == 1) {
                bf16* C = (bf16*)Cv;
                *(bf162*)(C + (size_t)mr * N + nc)       = __floats2bfloat162_rn(ox, oy);
                *(bf162*)(C + (size_t)(mr + 8) * N + nc) = __floats2bfloat162_rn(oz, ow);
            } else if (MODE == 0) {
                float* C = (float*)Cv;
                *(float2*)(C + (size_t)mr * N + nc)       = make_float2(ox, oy);
                *(float2*)(C + (size_t)(mr + 8) * N + nc) = make_float2(oz, ow);
            } else {
                // out = src3 + gamma1*(attn + gamma2*(acc+bias))
                float* C = (float*)Cv;
                float g1a = __ldg(gamma1 + nc), g1b = __ldg(gamma1 + nc + 1);
                float g2a = __ldg(gamma2 + nc), g2b = __ldg(gamma2 + nc + 1);
                float2 s0 = *(const float2*)(src3 + (size_t)mr * N + nc);
                float2 a0 = *(const float2*)(attn + (size_t)mr * N + nc);
                float2 s1 = *(const float2*)(src3 + (size_t)(mr + 8) * N + nc);
                float2 a1 = *(const float2*)(attn + (size_t)(mr + 8) * N + nc);
                *(float2*)(C + (size_t)mr * N + nc) =
                    make_float2(s0.x + g1a * (a0.x + g2a * ox), s0.y + g1b * (a0.y + g2b * oy));
                *(float2*)(C + (size_t)(mr + 8) * N + nc) =
                    make_float2(s1.x + g1a * (a1.x + g2a * oz), s1.y + g1b * (a1.y + g2b * ow));
            }
        }
    }
}

// ---------------- weight fp32 -> bf16 conversion ----------------
__global__ void __launch_bounds__(256) wcvt_kernel(
    const float* w0, const float* w1, const float* w2, const float* w3,
    const float* w4, const float* w5, const float* w6, const float* w7)
{
    int b = blockIdx.x;
    const float* src; bf16* dst;
    if      (b < 1024) { src = w0; dst = g_wbf + W_CAVW; }
    else if (b < 1536) { src = w1; dst = g_wbf + W_CAOW; b -= 1024; }
    else if (b < 1792) { src = w2; dst = g_wbf + W_CAAW; b -= 1536; }
    else if (b < 2816) { src = w3; dst = g_wbf + W_CAPW; b -= 1792; }
    else if (b < 3840) { src = w4; dst = g_wbf + W_SAVW; b -= 2816; }
    else if (b < 3968) { src = w5; dst = g_wbf + W_SAOW; b -= 3840; }
    else if (b < 4032) { src = w6; dst = g_wbf + W_SAAW; b -= 3968; }
    else               { src = w7; dst = g_wbf + W_SAPW; b -= 4032; }
    int idx = b * 1024 + threadIdx.x * 4;
    float4 v = *(const float4*)(src + idx);
    *(bf162*)(dst + idx)     = __floats2bfloat162_rn(v.x, v.y);
    *(bf162*)(dst + idx + 2) = __floats2bfloat162_rn(v.z, v.w);
}

// ---------------- layernorm -> bf16 out ----------------
__global__ void __launch_bounds__(256) layernorm_bf_kernel(
    const float* __restrict__ in, const float* __restrict__ g, const float* __restrict__ b,
    bf16* __restrict__ out)
{
    int r = blockIdx.x;
    const float* x = in + (size_t)r * DD;
    bf16* y = out + (size_t)r * DD;
    int t = threadIdx.x;

    float4 v = ((const float4*)x)[t];
    float s  = v.x + v.y + v.z + v.w;
    float ss = v.x*v.x + v.y*v.y + v.z*v.z + v.w*v.w;
    #pragma unroll
    for (int o = 16; o > 0; o >>= 1) {
        s  += __shfl_xor_sync(0xffffffffu, s,  o);
        ss += __shfl_xor_sync(0xffffffffu, ss, o);
    }
    __shared__ float sh_s[8], sh_ss[8];
    int wid = t >> 5, lane = t & 31;
    if (lane == 0) { sh_s[wid] = s; sh_ss[wid] = ss; }
    __syncthreads();
    s = 0.f; ss = 0.f;
    #pragma unroll
    for (int i = 0; i < 8; i++) { s += sh_s[i]; ss += sh_ss[i]; }
    float mean = s * (1.0f / DD);
    float var  = ss * (1.0f / DD) - mean * mean;
    float inv  = rsqrtf(var + 1e-6f);

    float4 gg = ((const float4*)g)[t];
    float4 bb2 = ((const float4*)b)[t];
    ((bf162*)y)[2*t]   = __floats2bfloat162_rn((v.x-mean)*inv*gg.x + bb2.x, (v.y-mean)*inv*gg.y + bb2.y);
    ((bf162*)y)[2*t+1] = __floats2bfloat162_rn((v.z-mean)*inv*gg.z + bb2.z, (v.w-mean)*inv*gg.w + bb2.w);
}

__global__ void __launch_bounds__(256) layernorm4_bf_kernel(
    const float* __restrict__ s0, const float* __restrict__ s1,
    const float* __restrict__ s2, const float* __restrict__ s3,
    const float* __restrict__ g, const float* __restrict__ b, bf16* __restrict__ out)
{
    int r = blockIdx.x;
    int level = r >> 12;
    int rr = r & 4095;
    const float* src = (level == 0) ? s0 : (level == 1) ? s1 : (level == 2) ? s2 : s3;
    const float* x = src + (size_t)rr * DD;
    int n = rr >> 10, q = rr & 1023;
    bf16* y = out + ((size_t)n * (4 * LQQ) + level * LQQ + q) * DD;
    int t = threadIdx.x;

    float4 v = ((const float4*)x)[t];
    float s  = v.x + v.y + v.z + v.w;
    float ss = v.x*v.x + v.y*v.y + v.z*v.z + v.w*v.w;
    #pragma unroll
    for (int o = 16; o > 0; o >>= 1) {
        s  += __shfl_xor_sync(0xffffffffu, s,  o);
        ss += __shfl_xor_sync(0xffffffffu, ss, o);
    }
    __shared__ float sh_s[8], sh_ss[8];
    int wid = t >> 5, lane = t & 31;
    if (lane == 0) { sh_s[wid] = s; sh_ss[wid] = ss; }
    __syncthreads();
    s = 0.f; ss = 0.f;
    #pragma unroll
    for (int i = 0; i < 8; i++) { s += sh_s[i]; ss += sh_ss[i]; }
    float mean = s * (1.0f / DD);
    float var  = ss * (1.0f / DD) - mean * mean;
    float inv  = rsqrtf(var + 1e-6f);

    float4 gg = ((const float4*)g)[t];
    float4 bb2 = ((const float4*)b)[t];
    ((bf162*)y)[2*t]   = __floats2bfloat162_rn((v.x-mean)*inv*gg.x + bb2.x, (v.y-mean)*inv*gg.y + bb2.y);
    ((bf162*)y)[2*t+1] = __floats2bfloat162_rn((v.z-mean)*inv*gg.z + bb2.z, (v.w-mean)*inv*gg.w + bb2.w);
}

// ---------------- softmax over P contiguous values ----------------
template<int P>
__global__ void softmax_kernel(float* __restrict__ w, int ngroups)
{
    int gid = blockIdx.x * blockDim.x + threadIdx.x;
    if (gid >= ngroups) return;
    float* p = w + (size_t)gid * P;
    float mx = p[0];
    #pragma unroll
    for (int i = 1; i < P; i++) mx = fmaxf(mx, p[i]);
    float s = 0.f;
    float e[P];
    #pragma unroll
    for (int i = 0; i < P; i++) { e[i] = __expf(p[i] - mx); s += e[i]; }
    float inv = 1.0f / s;
    #pragma unroll
    for (int i = 0; i < P; i++) p[i] = e[i] * inv;
}

// ---------------- deformable sampling (bf162 gathers, 2 channels/thread) ----------------
// block 256 thr = 8 heads x 32 lanes, grid (NH/8, LQ, B)
template<int NL>
__global__ void __launch_bounds__(256) sample_kernel(
    const bf16* __restrict__ val,
    const float* __restrict__ off,
    const float* __restrict__ attw,   // softmaxed
    bf16* __restrict__ out)
{
    const int h  = blockIdx.x * 8 + (threadIdx.x >> 5);
    const int lq = blockIdx.y;
    const int n  = blockIdx.z;
    const int c2 = threadIdx.x & 31;      // channel pair

    const float refx = ((lq & 31) + 0.5f) * 0.03125f;
    const float refy = ((lq >> 5) + 0.5f) * 0.03125f;

    const float* op = off  + (size_t)(n * LQQ + lq) * (NL * 128) + h * (NL * 8);
    const float* wp = attw + (size_t)(n * LQQ + lq) * (NL * 64)  + h * (NL * 4);
    const bf16* vb = val + (size_t)n * (NL * LQQ) * DD + h * DHH + 2 * c2;

    float accx = 0.f, accy = 0.f;
    #pragma unroll
    for (int l = 0; l < NL; l++) {
        const bf16* vl = vb + (size_t)l * LQQ * DD;
        #pragma unroll
        for (int p = 0; p < NPP; p++) {
            float ox = __ldg(op + l * 8 + p * 2 + 0);
            float oy = __ldg(op + l * 8 + p * 2 + 1);
            float x = (refx + ox * 0.03125f) * 32.f - 0.5f;
            float y = (refy + oy * 0.03125f) * 32.f - 0.5f;
            float x0f = floorf(x), y0f = floorf(y);
            int xi = (int)x0f, yi = (int)y0f;
            float fx = x - x0f, fy = y - y0f;
            float wv = __ldg(wp + l * 4 + p);
            float w00 = (1.f - fy) * (1.f - fx) * wv;
            float w01 = (1.f - fy) * fx * wv;
            float w10 = fy * (1.f - fx) * wv;
            float w11 = fy * fx * wv;
            bool xv0 = (xi >= 0) && (xi < 32);
            bool xv1 = (xi + 1 >= 0) && (xi + 1 < 32);
            if (yi >= 0 && yi < 32) {
                const bf16* row = vl + (size_t)yi * 32 * DD;
                if (xv0) { bf162 v2 = __ldg((const bf162*)(row + (size_t)xi * DD));
                           accx += w00 * __bfloat162float(v2.x); accy += w00 * __bfloat162float(v2.y); }
                if (xv1) { bf162 v2 = __ldg((const bf162*)(row + (size_t)(xi + 1) * DD));
                           accx += w01 * __bfloat162float(v2.x); accy += w01 * __bfloat162float(v2.y); }
            }
            if (yi + 1 >= 0 && yi + 1 < 32) {
                const bf16* row = vl + (size_t)(yi + 1) * 32 * DD;
                if (xv0) { bf162 v2 = __ldg((const bf162*)(row + (size_t)xi * DD));
                           accx += w10 * __bfloat162float(v2.x); accy += w10 * __bfloat162float(v2.y); }
                if (xv1) { bf162 v2 = __ldg((const bf162*)(row + (size_t)(xi + 1) * DD));
                           accx += w11 * __bfloat162float(v2.x); accy += w11 * __bfloat162float(v2.y); }
            }
        }
    }
    *(bf162*)(out + (size_t)(n * LQQ + lq) * DD + h * DHH + 2 * c2) = __floats2bfloat162_rn(accx, accy);
}

// ---------------- host launcher ----------------
extern "C" void kernel_launch(void* const* d_in, const int* in_sizes, int n_in,
                              void* d_out, int out_size)
{
    const float* src0 = (const float*)d_in[0];
    const float* src1 = (const float*)d_in[1];
    const float* src2 = (const float*)d_in[2];
    const float* src3 = (const float*)d_in[3];
    const float* qn_g = (const float*)d_in[4];
    const float* qn_b = (const float*)d_in[5];
    const float* fn_g = (const float*)d_in[6];
    const float* fn_b = (const float*)d_in[7];
    const float* n1_g = (const float*)d_in[8];
    const float* n1_b = (const float*)d_in[9];
    const float* gamma1 = (const float*)d_in[10];
    const float* gamma2 = (const float*)d_in[11];
    const float* ca_vw = (const float*)d_in[12];
    const float* ca_vb = (const float*)d_in[13];
    const float* ca_ow = (const float*)d_in[14];
    const float* ca_ob = (const float*)d_in[15];
    const float* ca_aw = (const float*)d_in[16];
    const float* ca_ab = (const float*)d_in[17];
    const float* ca_pw = (const float*)d_in[18];
    const float* ca_pb = (const float*)d_in[19];
    const float* sa_vw = (const float*)d_in[20];
    const float* sa_vb = (const float*)d_in[21];
    const float* sa_ow = (const float*)d_in[22];
    const float* sa_ob = (const float*)d_in[23];
    const float* sa_aw = (const float*)d_in[24];
    const float* sa_ab = (const float*)d_in[25];
    const float* sa_pw = (const float*)d_in[26];
    const float* sa_pb = (const float*)d_in[27];
    float* out = (float*)d_out;

    static bool attr_done = false;
    if (!attr_done) {
        cudaFuncSetAttribute(bf16_gemm_kernel<128,0>, cudaFuncAttributeMaxDynamicSharedMemorySize, 98304);
        cudaFuncSetAttribute(bf16_gemm_kernel<128,1>, cudaFuncAttributeMaxDynamicSharedMemorySize, 98304);
        cudaFuncSetAttribute(bf16_gemm_kernel<128,2>, cudaFuncAttributeMaxDynamicSharedMemorySize, 98304);
        cudaFuncSetAttribute(bf16_gemm_kernel<64,0>,  cudaFuncAttributeMaxDynamicSharedMemorySize, 73728);
        attr_done = true;
    }

    bf16 *qn, *fn, *wb, *val, *samp, *attn1, *val2, *samp2;
    float *off, *attw, *attn, *off2, *attw2;
    cudaGetSymbolAddress((void**)&qn,    g_qn_bf);
    cudaGetSymbolAddress((void**)&fn,    g_fn_bf);
    cudaGetSymbolAddress((void**)&wb,    g_wbf);
    cudaGetSymbolAddress((void**)&val,   g_val_bf);
    cudaGetSymbolAddress((void**)&off,   g_off);
    cudaGetSymbolAddress((void**)&attw,  g_attw);
    cudaGetSymbolAddress((void**)&samp,  g_samp_bf);
    cudaGetSymbolAddress((void**)&attn,  g_attn);
    cudaGetSymbolAddress((void**)&attn1, g_attn1_bf);
    cudaGetSymbolAddress((void**)&val2,  g_val2_bf);
    cudaGetSymbolAddress((void**)&off2,  g_off2);
    cudaGetSymbolAddress((void**)&attw2, g_attw2);
    cudaGetSymbolAddress((void**)&samp2, g_samp2_bf);

    const int ROWS_Q = BB * LQQ;        // 4096
    const int ROWS_F = BB * 4 * LQQ;    // 16384

    // 0) weights -> bf16
    wcvt_kernel<<<5056, 256>>>(ca_vw, ca_ow, ca_aw, ca_pw, sa_vw, sa_ow, sa_aw, sa_pw);

    // 1) layernorms (bf16 out)
    layernorm_bf_kernel<<<ROWS_Q, 256>>>(src3, qn_g, qn_b, qn);
    layernorm4_bf_kernel<<<4 * ROWS_Q, 256>>>(src0, src1, src2, src3, fn_g, fn_b, fn);

    // 2) CA projections
    bf16_gemm_kernel<128,1><<<dim3(8, 128), 128, 98304>>>(fn, wb + W_CAVW, ca_vb, val,  nullptr, nullptr, nullptr, nullptr, ROWS_F, DD,  DD);
    bf16_gemm_kernel<128,0><<<dim3(4, 32),  128, 98304>>>(qn, wb + W_CAOW, ca_ob, off,  nullptr, nullptr, nullptr, nullptr, ROWS_Q, 512, DD);
    bf16_gemm_kernel<128,0><<<dim3(2, 32),  128, 98304>>>(qn, wb + W_CAAW, ca_ab, attw, nullptr, nullptr, nullptr, nullptr, ROWS_Q, 256, DD);
    softmax_kernel<16><<<(BB * LQQ * NHH + 255) / 256, 256>>>(attw, BB * LQQ * NHH);

    // 3) CA sampling + output proj
    sample_kernel<4><<<dim3(NHH/8, LQQ, BB), 256>>>(val, off, attw, samp);
    bf16_gemm_kernel<128,0><<<dim3(8, 32), 128, 98304>>>(samp, wb + W_CAPW, ca_pb, attn, nullptr, nullptr, nullptr, nullptr, ROWS_Q, DD, DD);

    // 4) layernorm -> attn1 (bf16)
    layernorm_bf_kernel<<<ROWS_Q, 256>>>(attn, n1_g, n1_b, attn1);

    // 5) SA projections
    bf16_gemm_kernel<128,1><<<dim3(8, 32), 128, 98304>>>(attn1, wb + W_SAVW, sa_vb, val2,  nullptr, nullptr, nullptr, nullptr, ROWS_Q, DD,  DD);
    bf16_gemm_kernel<128,0><<<dim3(1, 32), 128, 98304>>>(attn1, wb + W_SAOW, sa_ob, off2,  nullptr, nullptr, nullptr, nullptr, ROWS_Q, 128, DD);
    bf16_gemm_kernel<64, 0><<<dim3(1, 32), 128, 73728>>>(attn1, wb + W_SAAW, sa_ab, attw2, nullptr, nullptr, nullptr, nullptr, ROWS_Q, 64,  DD);
    softmax_kernel<4><<<(BB * LQQ * NHH + 255) / 256, 256>>>(attw2, BB * LQQ * NHH);

    // 6) SA sampling + final proj with fused residual combine -> out
    sample_kernel<1><<<dim3(NHH/8, LQQ, BB), 256>>>(val2, off2, attw2, samp2);
    bf16_gemm_kernel<128,2><<<dim3(8, 32), 128, 98304>>>(samp2, wb + W_SAPW, sa_pb, out, src3, attn, gamma1, gamma2, ROWS_Q, DD, DD);
}

// round 13
// speedup vs baseline: 1.4648x; 1.0774x over previous
#include <cuda_runtime.h>
#include <cuda_bf16.h>
#include <math.h>
#include <stdint.h>

// Problem constants
#define BB 4
#define DD 1024
#define NHH 16
#define DHH 64
#define LQQ 1024
#define NPP 4

typedef __nv_bfloat16 bf16;
typedef __nv_bfloat162 bf162;

// ---------------- scratch (device globals; no allocation allowed) ----------------
__device__ bf16  g_qn_bf   [BB * LQQ * DD];
__device__ bf16  g_fn_bf   [BB * 4 * LQQ * DD];
__device__ bf16  g_wbf     [5177344];
__device__ float g_bca     [768];                   // [ca_ob | ca_ab]
__device__ float g_bsa     [192];                   // [sa_ob | sa_ab]
__device__ bf16  g_val_bf  [BB * 4 * LQQ * DD];
__device__ float g_ow      [BB * LQQ * 768];        // [off(512) | logits(256)] per row
__device__ bf16  g_samp_bf [BB * LQQ * DD];
__device__ float g_attn    [BB * LQQ * DD];
__device__ bf16  g_attn1_bf[BB * LQQ * DD];
__device__ bf16  g_val2_bf [BB * LQQ * DD];
__device__ float g_ow2     [BB * LQQ * 192];        // [off(128) | logits(64)]
__device__ bf16  g_samp2_bf[BB * LQQ * DD];

// weight offsets within g_wbf (ow/aw pairs are adjacent -> merged GEMMs)
#define W_CAVW 0
#define W_CAOW 1048576
#define W_CAPW 1835008
#define W_SAVW 2883584
#define W_SAOW 3932160
#define W_SAAW 4063232
#define W_SAPW 4128768
#define W_CAAW 1572864

// ---------------- helpers ----------------
__device__ __forceinline__ void mma_bf16(float4& d, const uint32_t* a, uint32_t b0, uint32_t b1) {
    asm("mma.sync.aligned.m16n8k16.row.col.f32.bf16.bf16.f32 "
        "{%0,%1,%2,%3}, {%4,%5,%6,%7}, {%8,%9}, {%0,%1,%2,%3};"
        : "+f"(d.x), "+f"(d.y), "+f"(d.z), "+f"(d.w)
        : "r"(a[0]), "r"(a[1]), "r"(a[2]), "r"(a[3]), "r"(b0), "r"(b1));
}

__device__ __forceinline__ void cp_async16(uint32_t dst, const void* src) {
    asm volatile("cp.async.cg.shared.global [%0], [%1], 16;" :: "r"(dst), "l"(src) : "memory");
}

__device__ __forceinline__ void ldsm4(uint32_t* r, uint32_t addr) {
    asm volatile("ldmatrix.sync.aligned.m8n8.x4.shared.b16 {%0,%1,%2,%3}, [%4];"
                 : "=r"(r[0]), "=r"(r[1]), "=r"(r[2]), "=r"(r[3]) : "r"(addr));
}

// ---------------- bf16 tensor-core GEMM: C[M,N] = A[M,K] @ W[N,K]^T + bias ----------------
// Block tile 128 x NT, BK=64, 128 threads = 4 warps in 2x2 (warp tile 64 x NT/2).
// 3-stage cp.async pipe. SMEM row = 128B; 16B chunk swizzle c' = c ^ (row&7).
// MODE: 0 = f32 out, 1 = bf16 out, 2 = fused residual combine (f32 out).
template<int NT, int MODE>
__global__ void __launch_bounds__(128, 2) bf16_gemm_kernel(
    const bf16* __restrict__ A, const bf16* __restrict__ W,
    const float* __restrict__ bias, void* __restrict__ Cv,
    const float* __restrict__ src3, const float* __restrict__ attn,
    const float* __restrict__ gamma1, const float* __restrict__ gamma2,
    int M, int N, int K)
{
    constexpr int NFRAG = NT / 16;
    constexpr int NPAIR = NFRAG / 2;
    constexpr int A_CH  = 8;
    constexpr int B_CH  = NT / 16;
    constexpr int ASZ   = 128 * 128;
    constexpr int BSZ   = NT * 128;
    constexpr int STG   = ASZ + BSZ;
    constexpr int S     = 3;

    extern __shared__ __align__(16) char dsm[];

    const int tid = threadIdx.x;
    const int lane = tid & 31;
    const int w = tid >> 5;
    const int warp_m = w >> 1;
    const int warp_n = w & 1;
    const int g = lane >> 2, t = lane & 3;
    const int m0 = blockIdx.y * 128;
    const int n0 = blockIdx.x * NT;

    const uint32_t smem_u32 = (uint32_t)__cvta_generic_to_shared(dsm);

    const int rowA = warp_m * 64 + (lane & 15);
    const int khA  = lane >> 4;
    const int swA  = rowA & 7;
    const int rowB = warp_n * (NT / 2) + ((lane >> 4) & 1) * 8 + (lane & 7);
    const int khB  = (lane >> 3) & 1;
    const int swB  = rowB & 7;
    uint32_t axo[4], bxo[4];
    #pragma unroll
    for (int ks = 0; ks < 4; ks++) {
        axo[ks] = (uint32_t)(((ks * 2 + khA) ^ swA) << 4);
        bxo[ks] = (uint32_t)(((ks * 2 + khB) ^ swB) << 4);
    }
    const uint32_t aBase = smem_u32 + rowA * 128;
    const uint32_t bBase = smem_u32 + ASZ + rowB * 128;

    float4 acc[4][NFRAG];
    #pragma unroll
    for (int i = 0; i < 4; i++)
        #pragma unroll
        for (int j = 0; j < NFRAG; j++) acc[i][j] = make_float4(0.f,0.f,0.f,0.f);

    auto issue = [&](int stage, int k0) {
        uint32_t sa = smem_u32 + stage * STG;
        uint32_t sb = sa + ASZ;
        #pragma unroll
        for (int i = 0; i < A_CH; i++) {
            int e = i * 128 + tid, row = e >> 3, c = e & 7;
            cp_async16(sa + row * 128 + ((c ^ (row & 7)) << 4),
                       A + (size_t)(m0 + row) * K + k0 + c * 8);
        }
        #pragma unroll
        for (int i = 0; i < B_CH; i++) {
            int e = i * 128 + tid, row = e >> 3, c = e & 7;
            cp_async16(sb + row * 128 + ((c ^ (row & 7)) << 4),
                       W + (size_t)(n0 + row) * K + k0 + c * 8);
        }
        asm volatile("cp.async.commit_group;" ::: "memory");
    };

    const int NCH = K >> 6;
    issue(0, 0); issue(1, 64);

    for (int it = 0; it < NCH; it++) {
        asm volatile("cp.async.wait_group 1;" ::: "memory");
        __syncthreads();
        if (it + 2 < NCH) issue((it + 2) % S, (it + 2) << 6);
        else asm volatile("cp.async.commit_group;" ::: "memory");

        const uint32_t stoff = (uint32_t)((it % S) * STG);

        #pragma unroll
        for (int ks = 0; ks < 4; ks++) {
            uint32_t a[4][4];
            uint32_t b[NPAIR][4];
            #pragma unroll
            for (int mf = 0; mf < 4; mf++)
                ldsm4(a[mf], aBase + stoff + mf * 2048 + axo[ks]);
            #pragma unroll
            for (int p = 0; p < NPAIR; p++)
                ldsm4(b[p], bBase + stoff + p * 2048 + bxo[ks]);
            #pragma unroll
            for (int mf = 0; mf < 4; mf++)
                #pragma unroll
                for (int nf = 0; nf < NFRAG; nf++)
                    mma_bf16(acc[mf][nf], a[mf], b[nf >> 1][(nf & 1) * 2], b[nf >> 1][(nf & 1) * 2 + 1]);
        }
    }

    // epilogue
    #pragma unroll
    for (int mf = 0; mf < 4; mf++) {
        int mr = m0 + warp_m*64 + mf*16 + g;
        #pragma unroll
        for (int nf = 0; nf < NFRAG; nf++) {
            int nc = n0 + warp_n*(NT/2) + nf*8 + 2*t;
            float b0 = __ldg(bias + nc), b1 = __ldg(bias + nc + 1);
            float ox = acc[mf][nf].x + b0, oy = acc[mf][nf].y + b1;
            float oz = acc[mf][nf].z + b0, ow = acc[mf][nf].w + b1;
            if (MODE == 1) {
                bf16* C = (bf16*)Cv;
                *(bf162*)(C + (size_t)mr * N + nc)       = __floats2bfloat162_rn(ox, oy);
                *(bf162*)(C + (size_t)(mr + 8) * N + nc) = __floats2bfloat162_rn(oz, ow);
            } else if (MODE == 0) {
                float* C = (float*)Cv;
                *(float2*)(C + (size_t)mr * N + nc)       = make_float2(ox, oy);
                *(float2*)(C + (size_t)(mr + 8) * N + nc) = make_float2(oz, ow);
            } else {
                float* C = (float*)Cv;
                float g1a = __ldg(gamma1 + nc), g1b = __ldg(gamma1 + nc + 1);
                float g2a = __ldg(gamma2 + nc), g2b = __ldg(gamma2 + nc + 1);
                float2 s0 = *(const float2*)(src3 + (size_t)mr * N + nc);
                float2 a0 = *(const float2*)(attn + (size_t)mr * N + nc);
                float2 s1 = *(const float2*)(src3 + (size_t)(mr + 8) * N + nc);
                float2 a1 = *(const float2*)(attn + (size_t)(mr + 8) * N + nc);
                *(float2*)(C + (size_t)mr * N + nc) =
                    make_float2(s0.x + g1a * (a0.x + g2a * ox), s0.y + g1b * (a0.y + g2b * oy));
                *(float2*)(C + (size_t)(mr + 8) * N + nc) =
                    make_float2(s1.x + g1a * (a1.x + g2a * oz), s1.y + g1b * (a1.y + g2b * ow));
            }
        }
    }
}

// ---------------- weight fp32 -> bf16 conversion + bias concat ----------------
__global__ void __launch_bounds__(256) wcvt_kernel(
    const float* w0, const float* w1, const float* w2, const float* w3,
    const float* w4, const float* w5, const float* w6, const float* w7,
    const float* ca_ob, const float* ca_ab, const float* sa_ob, const float* sa_ab)
{
    int b = blockIdx.x;
    if (b >= 5056) {
        if (b == 5056) {
            for (int i = threadIdx.x; i < 768; i += 256)
                g_bca[i] = (i < 512) ? ca_ob[i] : ca_ab[i - 512];
        } else {
            for (int i = threadIdx.x; i < 192; i += 256)
                g_bsa[i] = (i < 128) ? sa_ob[i] : sa_ab[i - 128];
        }
        return;
    }
    const float* src; bf16* dst;
    if      (b < 1024) { src = w0; dst = g_wbf + W_CAVW; }
    else if (b < 1536) { src = w1; dst = g_wbf + W_CAOW; b -= 1024; }
    else if (b < 1792) { src = w2; dst = g_wbf + W_CAAW; b -= 1536; }
    else if (b < 2816) { src = w3; dst = g_wbf + W_CAPW; b -= 1792; }
    else if (b < 3840) { src = w4; dst = g_wbf + W_SAVW; b -= 2816; }
    else if (b < 3968) { src = w5; dst = g_wbf + W_SAOW; b -= 3840; }
    else if (b < 4032) { src = w6; dst = g_wbf + W_SAAW; b -= 3968; }
    else               { src = w7; dst = g_wbf + W_SAPW; b -= 4032; }
    int idx = b * 1024 + threadIdx.x * 4;
    float4 v = *(const float4*)(src + idx);
    *(bf162*)(dst + idx)     = __floats2bfloat162_rn(v.x, v.y);
    *(bf162*)(dst + idx + 2) = __floats2bfloat162_rn(v.z, v.w);
}

// ---------------- warp-per-row layernorm (no smem, no syncthreads) ----------------
// block 256 = 8 warps = 8 rows; lane covers 8 float4 strided.
__device__ __forceinline__ void ln_row_core(
    const float* __restrict__ x, int lane, float4* v, float& mean, float& inv)
{
    float s = 0.f, ss = 0.f;
    #pragma unroll
    for (int i = 0; i < 8; i++) {
        v[i] = __ldg((const float4*)x + i * 32 + lane);
        s  += v[i].x + v[i].y + v[i].z + v[i].w;
        ss += v[i].x*v[i].x + v[i].y*v[i].y + v[i].z*v[i].z + v[i].w*v[i].w;
    }
    #pragma unroll
    for (int o = 16; o > 0; o >>= 1) {
        s  += __shfl_xor_sync(0xffffffffu, s,  o);
        ss += __shfl_xor_sync(0xffffffffu, ss, o);
    }
    mean = s * (1.0f / DD);
    float var = ss * (1.0f / DD) - mean * mean;
    inv = rsqrtf(var + 1e-6f);
}

__device__ __forceinline__ void ln_row_write_bf(
    bf16* __restrict__ y, int lane, const float4* v, float mean, float inv,
    const float* __restrict__ g, const float* __restrict__ b)
{
    #pragma unroll
    for (int i = 0; i < 8; i++) {
        int p = i * 32 + lane;                     // float4 index
        float4 gg = __ldg((const float4*)g + p);
        float4 bb = __ldg((const float4*)b + p);
        bf162 o0 = __floats2bfloat162_rn((v[i].x-mean)*inv*gg.x + bb.x, (v[i].y-mean)*inv*gg.y + bb.y);
        bf162 o1 = __floats2bfloat162_rn((v[i].z-mean)*inv*gg.z + bb.z, (v[i].w-mean)*inv*gg.w + bb.w);
        ((bf162*)y)[p*2]   = o0;
        ((bf162*)y)[p*2+1] = o1;
    }
}

// feat LN over 4 srcs -> fn; level-3 rows also produce qn (same stats, qn affine)
__global__ void __launch_bounds__(256) ln4q_kernel(
    const float* __restrict__ s0, const float* __restrict__ s1,
    const float* __restrict__ s2, const float* __restrict__ s3,
    const float* __restrict__ fng, const float* __restrict__ fnb,
    const float* __restrict__ qng, const float* __restrict__ qnb,
    bf16* __restrict__ fn, bf16* __restrict__ qn)
{
    int row = blockIdx.x * 8 + (threadIdx.x >> 5);   // 0..16383
    int lane = threadIdx.x & 31;
    int level = row >> 12;
    int rr = row & 4095;
    const float* src = (level == 0) ? s0 : (level == 1) ? s1 : (level == 2) ? s2 : s3;
    const float* x = src + (size_t)rr * DD;
    int n = rr >> 10, q = rr & 1023;

    float4 v[8]; float mean, inv;
    ln_row_core(x, lane, v, mean, inv);

    bf16* y = fn + ((size_t)n * (4 * LQQ) + level * LQQ + q) * DD;
    ln_row_write_bf(y, lane, v, mean, inv, fng, fnb);
    if (level == 3)
        ln_row_write_bf(qn + (size_t)rr * DD, lane, v, mean, inv, qng, qnb);
}

// generic warp-per-row LN, f32 in -> bf16 out
__global__ void __launch_bounds__(256) ln_rows_kernel(
    const float* __restrict__ in, const float* __restrict__ g, const float* __restrict__ b,
    bf16* __restrict__ out)
{
    int row = blockIdx.x * 8 + (threadIdx.x >> 5);
    int lane = threadIdx.x & 31;
    const float* x = in + (size_t)row * DD;
    float4 v[8]; float mean, inv;
    ln_row_core(x, lane, v, mean, inv);
    ln_row_write_bf(out + (size_t)row * DD, lane, v, mean, inv, g, b);
}

// ---------------- softmax over P contiguous values in strided merged buffer ----------------
// row stride RS, logits start at COFF, group h at COFF + h*P
template<int P, int RS, int COFF>
__global__ void softmax_kernel(float* __restrict__ w, int ngroups)
{
    int gid = blockIdx.x * blockDim.x + threadIdx.x;
    if (gid >= ngroups) return;
    int row = gid >> 4, h = gid & 15;           // NH=16
    float* p = w + (size_t)row * RS + COFF + h * P;
    float mx = p[0];
    #pragma unroll
    for (int i = 1; i < P; i++) mx = fmaxf(mx, p[i]);
    float s = 0.f;
    float e[P];
    #pragma unroll
    for (int i = 0; i < P; i++) { e[i] = __expf(p[i] - mx); s += e[i]; }
    float inv = 1.0f / s;
    #pragma unroll
    for (int i = 0; i < P; i++) p[i] = e[i] * inv;
}

// ---------------- deformable sampling (merged off/logits buffer) ----------------
// block 256 thr = 8 heads x 32 lanes, grid (NH/8, LQ, B); RS = NL*192, LOGOFF = NL*128
template<int NL>
__global__ void __launch_bounds__(256) sample_kernel(
    const bf16* __restrict__ val,
    const float* __restrict__ ow,
    bf16* __restrict__ out)
{
    constexpr int RS = NL * 192;
    constexpr int LOGOFF = NL * 128;
    const int h  = blockIdx.x * 8 + (threadIdx.x >> 5);
    const int lq = blockIdx.y;
    const int n  = blockIdx.z;
    const int c2 = threadIdx.x & 31;

    const float refx = ((lq & 31) + 0.5f) * 0.03125f;
    const float refy = ((lq >> 5) + 0.5f) * 0.03125f;

    const float* op = ow + (size_t)(n * LQQ + lq) * RS + h * (NL * 8);
    const float* wp = ow + (size_t)(n * LQQ + lq) * RS + LOGOFF + h * (NL * 4);
    const bf16* vb = val + (size_t)n * (NL * LQQ) * DD + h * DHH + 2 * c2;

    float accx = 0.f, accy = 0.f;
    #pragma unroll
    for (int l = 0; l < NL; l++) {
        const bf16* vl = vb + (size_t)l * LQQ * DD;
        #pragma unroll
        for (int p = 0; p < NPP; p++) {
            float ox = __ldg(op + l * 8 + p * 2 + 0);
            float oy = __ldg(op + l * 8 + p * 2 + 1);
            float x = (refx + ox * 0.03125f) * 32.f - 0.5f;
            float y = (refy + oy * 0.03125f) * 32.f - 0.5f;
            float x0f = floorf(x), y0f = floorf(y);
            int xi = (int)x0f, yi = (int)y0f;
            float fx = x - x0f, fy = y - y0f;
            float wv = __ldg(wp + l * 4 + p);
            float w00 = (1.f - fy) * (1.f - fx) * wv;
            float w01 = (1.f - fy) * fx * wv;
            float w10 = fy * (1.f - fx) * wv;
            float w11 = fy * fx * wv;
            bool xv0 = (xi >= 0) && (xi < 32);
            bool xv1 = (xi + 1 >= 0) && (xi + 1 < 32);
            if (yi >= 0 && yi < 32) {
                const bf16* row = vl + (size_t)yi * 32 * DD;
                if (xv0) { bf162 v2 = __ldg((const bf162*)(row + (size_t)xi * DD));
                           accx += w00 * __bfloat162float(v2.x); accy += w00 * __bfloat162float(v2.y); }
                if (xv1) { bf162 v2 = __ldg((const bf162*)(row + (size_t)(xi + 1) * DD));
                           accx += w01 * __bfloat162float(v2.x); accy += w01 * __bfloat162float(v2.y); }
            }
            if (yi + 1 >= 0 && yi + 1 < 32) {
                const bf16* row = vl + (size_t)(yi + 1) * 32 * DD;
                if (xv0) { bf162 v2 = __ldg((const bf162*)(row + (size_t)xi * DD));
                           accx += w10 * __bfloat162float(v2.x); accy += w10 * __bfloat162float(v2.y); }
                if (xv1) { bf162 v2 = __ldg((const bf162*)(row + (size_t)(xi + 1) * DD));
                           accx += w11 * __bfloat162float(v2.x); accy += w11 * __bfloat162float(v2.y); }
            }
        }
    }
    *(bf162*)(out + (size_t)(n * LQQ + lq) * DD + h * DHH + 2 * c2) = __floats2bfloat162_rn(accx, accy);
}

// ---------------- host launcher ----------------
extern "C" void kernel_launch(void* const* d_in, const int* in_sizes, int n_in,
                              void* d_out, int out_size)
{
    const float* src0 = (const float*)d_in[0];
    const float* src1 = (const float*)d_in[1];
    const float* src2 = (const float*)d_in[2];
    const float* src3 = (const float*)d_in[3];
    const float* qn_g = (const float*)d_in[4];
    const float* qn_b = (const float*)d_in[5];
    const float* fn_g = (const float*)d_in[6];
    const float* fn_b = (const float*)d_in[7];
    const float* n1_g = (const float*)d_in[8];
    const float* n1_b = (const float*)d_in[9];
    const float* gamma1 = (const float*)d_in[10];
    const float* gamma2 = (const float*)d_in[11];
    const float* ca_vw = (const float*)d_in[12];
    const float* ca_vb = (const float*)d_in[13];
    const float* ca_ow = (const float*)d_in[14];
    const float* ca_ob = (const float*)d_in[15];
    const float* ca_aw = (const float*)d_in[16];
    const float* ca_ab = (const float*)d_in[17];
    const float* ca_pw = (const float*)d_in[18];
    const float* ca_pb = (const float*)d_in[19];
    const float* sa_vw = (const float*)d_in[20];
    const float* sa_vb = (const float*)d_in[21];
    const float* sa_ow = (const float*)d_in[22];
    const float* sa_ob = (const float*)d_in[23];
    const float* sa_aw = (const float*)d_in[24];
    const float* sa_ab = (const float*)d_in[25];
    const float* sa_pw = (const float*)d_in[26];
    const float* sa_pb = (const float*)d_in[27];
    float* out = (float*)d_out;

    static bool attr_done = false;
    if (!attr_done) {
        cudaFuncSetAttribute(bf16_gemm_kernel<128,0>, cudaFuncAttributeMaxDynamicSharedMemorySize, 98304);
        cudaFuncSetAttribute(bf16_gemm_kernel<128,1>, cudaFuncAttributeMaxDynamicSharedMemorySize, 98304);
        cudaFuncSetAttribute(bf16_gemm_kernel<128,2>, cudaFuncAttributeMaxDynamicSharedMemorySize, 98304);
        cudaFuncSetAttribute(bf16_gemm_kernel<64,0>,  cudaFuncAttributeMaxDynamicSharedMemorySize, 73728);
        attr_done = true;
    }

    bf16 *qn, *fn, *wb, *val, *samp, *attn1, *val2, *samp2;
    float *ow, *attn, *ow2, *bca, *bsa;
    cudaGetSymbolAddress((void**)&qn,    g_qn_bf);
    cudaGetSymbolAddress((void**)&fn,    g_fn_bf);
    cudaGetSymbolAddress((void**)&wb,    g_wbf);
    cudaGetSymbolAddress((void**)&bca,   g_bca);
    cudaGetSymbolAddress((void**)&bsa,   g_bsa);
    cudaGetSymbolAddress((void**)&val,   g_val_bf);
    cudaGetSymbolAddress((void**)&ow,    g_ow);
    cudaGetSymbolAddress((void**)&samp,  g_samp_bf);
    cudaGetSymbolAddress((void**)&attn,  g_attn);
    cudaGetSymbolAddress((void**)&attn1, g_attn1_bf);
    cudaGetSymbolAddress((void**)&val2,  g_val2_bf);
    cudaGetSymbolAddress((void**)&ow2,   g_ow2);
    cudaGetSymbolAddress((void**)&samp2, g_samp2_bf);

    const int ROWS_Q = BB * LQQ;        // 4096
    const int ROWS_F = BB * 4 * LQQ;    // 16384

    // 0) weights -> bf16 + bias concat
    wcvt_kernel<<<5058, 256>>>(ca_vw, ca_ow, ca_aw, ca_pw, sa_vw, sa_ow, sa_aw, sa_pw,
                               ca_ob, ca_ab, sa_ob, sa_ab);

    // 1) fused feat+query layernorm (fn all levels; qn from level-3 stats)
    ln4q_kernel<<<ROWS_F / 8, 256>>>(src0, src1, src2, src3, fn_g, fn_b, qn_g, qn_b, fn, qn);

    // 2) CA projections: value + merged [off|logits]
    bf16_gemm_kernel<128,1><<<dim3(8, 128), 128, 98304>>>(fn, wb + W_CAVW, ca_vb, val, nullptr, nullptr, nullptr, nullptr, ROWS_F, DD,  DD);
    bf16_gemm_kernel<128,0><<<dim3(6, 32),  128, 98304>>>(qn, wb + W_CAOW, bca,   ow,  nullptr, nullptr, nullptr, nullptr, ROWS_Q, 768, DD);
    softmax_kernel<16, 768, 512><<<(BB * LQQ * NHH + 255) / 256, 256>>>(ow, BB * LQQ * NHH);

    // 3) CA sampling + output proj
    sample_kernel<4><<<dim3(NHH/8, LQQ, BB), 256>>>(val, ow, samp);
    bf16_gemm_kernel<128,0><<<dim3(8, 32), 128, 98304>>>(samp, wb + W_CAPW, ca_pb, attn, nullptr, nullptr, nullptr, nullptr, ROWS_Q, DD, DD);

    // 4) layernorm -> attn1 (bf16)
    ln_rows_kernel<<<ROWS_Q / 8, 256>>>(attn, n1_g, n1_b, attn1);

    // 5) SA projections: value + merged [off|logits]
    bf16_gemm_kernel<128,1><<<dim3(8, 32), 128, 98304>>>(attn1, wb + W_SAVW, sa_vb, val2, nullptr, nullptr, nullptr, nullptr, ROWS_Q, DD,  DD);
    bf16_gemm_kernel<64, 0><<<dim3(3, 32), 128, 73728>>>(attn1, wb + W_SAOW, bsa,   ow2,  nullptr, nullptr, nullptr, nullptr, ROWS_Q, 192, DD);
    softmax_kernel<4, 192, 128><<<(BB * LQQ * NHH + 255) / 256, 256>>>(ow2, BB * LQQ * NHH);

    // 6) SA sampling + final proj with fused residual combine -> out
    sample_kernel<1><<<dim3(NHH/8, LQQ, BB), 256>>>(val2, ow2, samp2);
    bf16_gemm_kernel<128,2><<<dim3(8, 32), 128, 98304>>>(samp2, wb + W_SAPW, sa_pb, out, src3, attn, gamma1, gamma2, ROWS_Q, DD, DD);
}